// round 1
// baseline (speedup 1.0000x reference)
#include <cuda_runtime.h>
#include <math.h>

#define BATCH 2
#define NSEQ  2048
#define DIM   1024
#define HEADS 16
#define DHEAD 64
#define INNER 1024
#define ROWS  (BATCH*NSEQ)   // 4096
#define QKVW  (3*INNER)      // 3072
#define ATT_SCALE 8.0f
#define LN_EPS 1e-5f

// Scratch (static device allocations — allowed by harness rules)
__device__ float g_xn [ (size_t)ROWS * DIM  ];
__device__ float g_qkv[ (size_t)ROWS * QKVW ];
__device__ float g_oat[ (size_t)ROWS * INNER];

// ---------------------------------------------------------------------------
// LayerNorm: one block (256 thr) per row of 1024
// ---------------------------------------------------------------------------
__global__ __launch_bounds__(256) void ln_kernel(
    const float* __restrict__ x, const float* __restrict__ w,
    const float* __restrict__ b, float* __restrict__ out)
{
    int row = blockIdx.x;
    int tid = threadIdx.x;
    const float4 v = ((const float4*)(x + (size_t)row * DIM))[tid];
    float s  = v.x + v.y + v.z + v.w;
    float ss = v.x*v.x + v.y*v.y + v.z*v.z + v.w*v.w;
    #pragma unroll
    for (int o = 16; o; o >>= 1) {
        s  += __shfl_xor_sync(0xffffffffu, s,  o);
        ss += __shfl_xor_sync(0xffffffffu, ss, o);
    }
    __shared__ float sh_s[8], sh_ss[8];
    int wid = tid >> 5, lane = tid & 31;
    if (lane == 0) { sh_s[wid] = s; sh_ss[wid] = ss; }
    __syncthreads();
    if (tid == 0) {
        float a = 0.f, q = 0.f;
        #pragma unroll
        for (int i = 0; i < 8; i++) { a += sh_s[i]; q += sh_ss[i]; }
        sh_s[0] = a; sh_ss[0] = q;
    }
    __syncthreads();
    float mu   = sh_s[0]  * (1.0f / DIM);
    float var  = sh_ss[0] * (1.0f / DIM) - mu * mu;
    float rstd = rsqrtf(var + LN_EPS);
    float4 w4 = ((const float4*)w)[tid];
    float4 b4 = ((const float4*)b)[tid];
    float4 o4;
    o4.x = (v.x - mu) * rstd * w4.x + b4.x;
    o4.y = (v.y - mu) * rstd * w4.y + b4.y;
    o4.z = (v.z - mu) * rstd * w4.z + b4.z;
    o4.w = (v.w - mu) * rstd * w4.w + b4.w;
    ((float4*)(out + (size_t)row * DIM))[tid] = o4;
}

// ---------------------------------------------------------------------------
// Tiled fp32 SGEMM: C[M,N] = A[M,K] @ B[K,N], all row-major,
// BM=BN=64, BK=16, 256 threads, 4x4 micro-tile per thread.
// Dims must be multiples of 64 (they are: 4096/3072/1024).
// ---------------------------------------------------------------------------
__global__ __launch_bounds__(256) void sgemm_kernel(
    const float* __restrict__ A, const float* __restrict__ B,
    float* __restrict__ C, int M, int N, int K)
{
    __shared__ float As[16][64];
    __shared__ float Bs[16][64];
    int tid = threadIdx.x;
    int bx = blockIdx.x, by = blockIdx.y;
    int trow = (tid >> 4) << 2;   // 0..60
    int tcol = (tid & 15) << 2;   // 0..60
    int arow = tid >> 2;          // 0..63
    int acol = (tid & 3) << 2;    // 0,4,8,12
    int brow = tid >> 4;          // 0..15
    int bcol = (tid & 15) << 2;   // 0..60

    const float* Ap = A + (size_t)(by * 64 + arow) * K + acol;
    const float* Bp = B + (size_t)brow * N + (size_t)bx * 64 + bcol;

    float acc[4][4];
    #pragma unroll
    for (int i = 0; i < 4; i++)
        #pragma unroll
        for (int j = 0; j < 4; j++) acc[i][j] = 0.f;

    for (int k0 = 0; k0 < K; k0 += 16) {
        float4 a4 = *(const float4*)(Ap + k0);
        float4 b4 = *(const float4*)(Bp + (size_t)k0 * N);
        As[acol + 0][arow] = a4.x;
        As[acol + 1][arow] = a4.y;
        As[acol + 2][arow] = a4.z;
        As[acol + 3][arow] = a4.w;
        *(float4*)&Bs[brow][bcol] = b4;
        __syncthreads();
        #pragma unroll
        for (int kk = 0; kk < 16; kk++) {
            float4 a = *(const float4*)&As[kk][trow];
            float4 b = *(const float4*)&Bs[kk][tcol];
            acc[0][0] += a.x*b.x; acc[0][1] += a.x*b.y; acc[0][2] += a.x*b.z; acc[0][3] += a.x*b.w;
            acc[1][0] += a.y*b.x; acc[1][1] += a.y*b.y; acc[1][2] += a.y*b.z; acc[1][3] += a.y*b.w;
            acc[2][0] += a.z*b.x; acc[2][1] += a.z*b.y; acc[2][2] += a.z*b.z; acc[2][3] += a.z*b.w;
            acc[3][0] += a.w*b.x; acc[3][1] += a.w*b.y; acc[3][2] += a.w*b.z; acc[3][3] += a.w*b.w;
        }
        __syncthreads();
    }
    float* Cp = C + (size_t)(by * 64 + trow) * N + (size_t)bx * 64 + tcol;
    #pragma unroll
    for (int i = 0; i < 4; i++) {
        float4 st; st.x = acc[i][0]; st.y = acc[i][1]; st.z = acc[i][2]; st.w = acc[i][3];
        *(float4*)(Cp + (size_t)i * N) = st;
    }
}

// ---------------------------------------------------------------------------
// L2-normalize q and k head-vectors in-place inside qkv scratch.
// One warp per 64-dim vector. Vectors: ROWS * HEADS * 2 = 131072.
// ---------------------------------------------------------------------------
__global__ __launch_bounds__(256) void l2norm_kernel(float* __restrict__ qkv)
{
    int warp = (blockIdx.x << 3) + (threadIdx.x >> 5);
    int lane = threadIdx.x & 31;
    int row  = warp >> 5;        // /32  (16 heads * 2)
    int rem  = warp & 31;
    float* base = qkv + (size_t)row * QKVW + (size_t)(rem >> 4) * INNER + (size_t)(rem & 15) * DHEAD;
    float x0 = base[lane];
    float x1 = base[lane + 32];
    float ss = x0*x0 + x1*x1;
    #pragma unroll
    for (int o = 16; o; o >>= 1) ss += __shfl_xor_sync(0xffffffffu, ss, o);
    float inv = 1.0f / fmaxf(sqrtf(ss), 1e-12f);
    base[lane]      = x0 * inv;
    base[lane + 32] = x1 * inv;
}

// ---------------------------------------------------------------------------
// Flash-style causal attention, fp32.
// Grid: (NSEQ/64, HEADS, BATCH). Block: 256 threads.
// Smem: Qt[64d][68], Kt[64d][68] (d-major), Vs[64kk][68], Ss[64row][68].
// Thread (rg,cg) owns score micro-tile rows r0..r0+3 x keys c0..c0+3,
// and output micro-tile rows r0..r0+3 x dims c0..c0+3.
// ---------------------------------------------------------------------------
#define TPAD 68
#define ATT_SMEM_BYTES (4 * 64 * TPAD * 4)

__global__ __launch_bounds__(256) void attn_kernel(
    const float* __restrict__ qkv, float* __restrict__ oat)
{
    extern __shared__ float sm[];
    float* Qt = sm;                  // [d][row]
    float* Kt = sm + 64 * TPAD;      // [d][key]
    float* Vs = sm + 2 * 64 * TPAD;  // [key][d]
    float* Ss = sm + 3 * 64 * TPAD;  // [row][key]

    int tid = threadIdx.x;
    int qt = blockIdx.x, h = blockIdx.y, bb = blockIdx.z;
    int row0 = qt * 64;
    size_t rowbase = (size_t)bb * NSEQ;

    int rg = tid >> 4, cg = tid & 15;
    int r0 = rg << 2, c0 = cg << 2;

    // Load Q tile, transposed to d-major
    for (int e = tid; e < 64 * 16; e += 256) {
        int i  = e >> 4;
        int d0 = (e & 15) << 2;
        float4 q4 = *(const float4*)(qkv + (rowbase + row0 + i) * QKVW + h * DHEAD + d0);
        Qt[(d0 + 0) * TPAD + i] = q4.x;
        Qt[(d0 + 1) * TPAD + i] = q4.y;
        Qt[(d0 + 2) * TPAD + i] = q4.z;
        Qt[(d0 + 3) * TPAD + i] = q4.w;
    }

    float m[4], l[4], o[4][4];
    #pragma unroll
    for (int i = 0; i < 4; i++) {
        m[i] = -INFINITY; l[i] = 0.f;
        #pragma unroll
        for (int j = 0; j < 4; j++) o[i][j] = 0.f;
    }

    for (int jt = 0; jt <= qt; jt++) {
        int j0 = jt * 64;
        __syncthreads();   // prior-iteration smem reads done
        for (int e = tid; e < 64 * 16; e += 256) {
            int i  = e >> 4;
            int d0 = (e & 15) << 2;
            const float* src = qkv + (rowbase + j0 + i) * QKVW + h * DHEAD + d0;
            float4 k4 = *(const float4*)(src + INNER);
            Kt[(d0 + 0) * TPAD + i] = k4.x;
            Kt[(d0 + 1) * TPAD + i] = k4.y;
            Kt[(d0 + 2) * TPAD + i] = k4.z;
            Kt[(d0 + 3) * TPAD + i] = k4.w;
            float4 v4 = *(const float4*)(src + 2 * INNER);
            *(float4*)&Vs[i * TPAD + d0] = v4;
        }
        __syncthreads();

        // ---- scores: acc[i][j] = q(r0+i) . k(c0+j) ----
        float acc[4][4];
        #pragma unroll
        for (int i = 0; i < 4; i++)
            #pragma unroll
            for (int j = 0; j < 4; j++) acc[i][j] = 0.f;

        #pragma unroll 16
        for (int d = 0; d < 64; d++) {
            float4 kv = *(const float4*)&Kt[d * TPAD + c0];
            float4 qv = *(const float4*)&Qt[d * TPAD + r0];
            acc[0][0] += qv.x*kv.x; acc[0][1] += qv.x*kv.y; acc[0][2] += qv.x*kv.z; acc[0][3] += qv.x*kv.w;
            acc[1][0] += qv.y*kv.x; acc[1][1] += qv.y*kv.y; acc[1][2] += qv.y*kv.z; acc[1][3] += qv.y*kv.w;
            acc[2][0] += qv.z*kv.x; acc[2][1] += qv.z*kv.y; acc[2][2] += qv.z*kv.z; acc[2][3] += qv.z*kv.w;
            acc[3][0] += qv.w*kv.x; acc[3][1] += qv.w*kv.y; acc[3][2] += qv.w*kv.z; acc[3][3] += qv.w*kv.w;
        }

        #pragma unroll
        for (int i = 0; i < 4; i++)
            #pragma unroll
            for (int j = 0; j < 4; j++) acc[i][j] *= ATT_SCALE;

        if (jt == qt) {  // diagonal tile: causal mask (c0+j > r0+i -> masked)
            #pragma unroll
            for (int i = 0; i < 4; i++)
                #pragma unroll
                for (int j = 0; j < 4; j++)
                    if (c0 + j > r0 + i) acc[i][j] = -INFINITY;
        }

        // ---- online softmax per row ----
        #pragma unroll
        for (int i = 0; i < 4; i++) {
            float mt = fmaxf(fmaxf(acc[i][0], acc[i][1]), fmaxf(acc[i][2], acc[i][3]));
            mt = fmaxf(mt, __shfl_xor_sync(0xffffffffu, mt, 1));
            mt = fmaxf(mt, __shfl_xor_sync(0xffffffffu, mt, 2));
            mt = fmaxf(mt, __shfl_xor_sync(0xffffffffu, mt, 4));
            mt = fmaxf(mt, __shfl_xor_sync(0xffffffffu, mt, 8));
            float mn = fmaxf(m[i], mt);
            float corr = __expf(m[i] - mn);
            m[i] = mn;
            l[i] *= corr;
            #pragma unroll
            for (int j = 0; j < 4; j++) o[i][j] *= corr;
            float4 p;
            p.x = __expf(acc[i][0] - mn);
            p.y = __expf(acc[i][1] - mn);
            p.z = __expf(acc[i][2] - mn);
            p.w = __expf(acc[i][3] - mn);
            float ls = p.x + p.y + p.z + p.w;
            *(float4*)&Ss[(r0 + i) * TPAD + c0] = p;
            ls += __shfl_xor_sync(0xffffffffu, ls, 1);
            ls += __shfl_xor_sync(0xffffffffu, ls, 2);
            ls += __shfl_xor_sync(0xffffffffu, ls, 4);
            ls += __shfl_xor_sync(0xffffffffu, ls, 8);
            l[i] += ls;
        }
        __syncwarp();   // Ss produced/consumed within the same warp's 16-lane groups

        // ---- PV: o[i][j] += sum_kk P[r0+i][kk] * V[kk][c0+j] ----
        #pragma unroll 8
        for (int kk = 0; kk < 64; kk++) {
            float4 vv = *(const float4*)&Vs[kk * TPAD + c0];
            float p0 = Ss[(r0 + 0) * TPAD + kk];
            float p1 = Ss[(r0 + 1) * TPAD + kk];
            float p2 = Ss[(r0 + 2) * TPAD + kk];
            float p3 = Ss[(r0 + 3) * TPAD + kk];
            o[0][0] += p0*vv.x; o[0][1] += p0*vv.y; o[0][2] += p0*vv.z; o[0][3] += p0*vv.w;
            o[1][0] += p1*vv.x; o[1][1] += p1*vv.y; o[1][2] += p1*vv.z; o[1][3] += p1*vv.w;
            o[2][0] += p2*vv.x; o[2][1] += p2*vv.y; o[2][2] += p2*vv.z; o[2][3] += p2*vv.w;
            o[3][0] += p3*vv.x; o[3][1] += p3*vv.y; o[3][2] += p3*vv.z; o[3][3] += p3*vv.w;
        }
    }

    // ---- epilogue: divide by l, write [b, n, h*d] ----
    #pragma unroll
    for (int i = 0; i < 4; i++) {
        float inv = 1.0f / l[i];
        float4 st;
        st.x = o[i][0] * inv; st.y = o[i][1] * inv;
        st.z = o[i][2] * inv; st.w = o[i][3] * inv;
        *(float4*)(oat + (rowbase + row0 + r0 + i) * INNER + h * DHEAD + c0) = st;
    }
}

// ---------------------------------------------------------------------------
extern "C" void kernel_launch(void* const* d_in, const int* in_sizes, int n_in,
                              void* d_out, int out_size)
{
    const float* x    = (const float*)d_in[0];
    const float* lnw  = (const float*)d_in[1];
    const float* lnb  = (const float*)d_in[2];
    const float* Wqkv = (const float*)d_in[3];
    const float* Wout = (const float*)d_in[4];
    float* out = (float*)d_out;

    float *xn, *qkvp, *oat;
    cudaGetSymbolAddress((void**)&xn,   g_xn);
    cudaGetSymbolAddress((void**)&qkvp, g_qkv);
    cudaGetSymbolAddress((void**)&oat,  g_oat);

    ln_kernel<<<ROWS, 256>>>(x, lnw, lnb, xn);

    dim3 g1(QKVW / 64, ROWS / 64);
    sgemm_kernel<<<g1, 256>>>(xn, Wqkv, qkvp, ROWS, QKVW, DIM);

    l2norm_kernel<<<(ROWS * HEADS * 2) / 8, 256>>>(qkvp);

    cudaFuncSetAttribute(attn_kernel, cudaFuncAttributeMaxDynamicSharedMemorySize, ATT_SMEM_BYTES);
    attn_kernel<<<dim3(NSEQ / 64, HEADS, BATCH), 256, ATT_SMEM_BYTES>>>(qkvp, oat);

    dim3 g2(INNER / 64, ROWS / 64);
    sgemm_kernel<<<g2, 256>>>(oat, Wout, out, ROWS, INNER, DIM);
}

// round 3
// speedup vs baseline: 1.6330x; 1.6330x over previous
#include <cuda_runtime.h>
#include <math.h>
#include <stdint.h>

#define BATCH 2
#define NSEQ  2048
#define DIM   1024
#define HEADS 16
#define DHEAD 64
#define INNER 1024
#define ROWS  (BATCH*NSEQ)   // 4096
#define QKVW  (3*INNER)      // 3072
#define ATT_SCALE 8.0f
#define LN_EPS 1e-5f

// Scratch (static device allocations — allowed)
__device__ float g_xn   [(size_t)ROWS * DIM  ];
__device__ float g_qkv  [(size_t)ROWS * QKVW ];
__device__ float g_oat  [(size_t)ROWS * INNER];
__device__ float g_wqkvT[(size_t)QKVW * DIM  ];
__device__ float g_woutT[(size_t)INNER * DIM ];

// ===========================================================================
// LayerNorm: one block (256 thr) per row of 1024
// ===========================================================================
__global__ __launch_bounds__(256) void ln_kernel(
    const float* __restrict__ x, const float* __restrict__ w,
    const float* __restrict__ b, float* __restrict__ out)
{
    int row = blockIdx.x;
    int tid = threadIdx.x;
    const float4 v = ((const float4*)(x + (size_t)row * DIM))[tid];
    float s  = v.x + v.y + v.z + v.w;
    float ss = v.x*v.x + v.y*v.y + v.z*v.z + v.w*v.w;
    #pragma unroll
    for (int o = 16; o; o >>= 1) {
        s  += __shfl_xor_sync(0xffffffffu, s,  o);
        ss += __shfl_xor_sync(0xffffffffu, ss, o);
    }
    __shared__ float sh_s[8], sh_ss[8];
    int wid = tid >> 5, lane = tid & 31;
    if (lane == 0) { sh_s[wid] = s; sh_ss[wid] = ss; }
    __syncthreads();
    if (tid == 0) {
        float a = 0.f, q = 0.f;
        #pragma unroll
        for (int i = 0; i < 8; i++) { a += sh_s[i]; q += sh_ss[i]; }
        sh_s[0] = a; sh_ss[0] = q;
    }
    __syncthreads();
    float mu   = sh_s[0]  * (1.0f / DIM);
    float var  = sh_ss[0] * (1.0f / DIM) - mu * mu;
    float rstd = rsqrtf(var + LN_EPS);
    float4 w4 = ((const float4*)w)[tid];
    float4 b4 = ((const float4*)b)[tid];
    float4 o4;
    o4.x = (v.x - mu) * rstd * w4.x + b4.x;
    o4.y = (v.y - mu) * rstd * w4.y + b4.y;
    o4.z = (v.z - mu) * rstd * w4.z + b4.z;
    o4.w = (v.w - mu) * rstd * w4.w + b4.w;
    ((float4*)(out + (size_t)row * DIM))[tid] = o4;
}

// ===========================================================================
// 32x32 smem transpose: out[c*R + r] = in[r*C + c]
// ===========================================================================
__global__ __launch_bounds__(256) void transpose_kernel(
    const float* __restrict__ in, float* __restrict__ out, int R, int C)
{
    __shared__ float t[32][33];
    int c0 = blockIdx.x << 5, r0 = blockIdx.y << 5;
    int tx = threadIdx.x & 31, ty = threadIdx.x >> 5;
    #pragma unroll
    for (int i = 0; i < 4; i++) {
        int r = ty + i * 8;
        t[r][tx] = in[(size_t)(r0 + r) * C + c0 + tx];
    }
    __syncthreads();
    #pragma unroll
    for (int i = 0; i < 4; i++) {
        int r = ty + i * 8;
        out[(size_t)(c0 + r) * R + r0 + tx] = t[tx][r];
    }
}

// ===========================================================================
// tf32 mma.sync GEMM: C[M,N] = A[M,K] @ Bt[N,K]^T (A, Bt row-major)
// CTA tile 128x128, BK=32, 256 threads (8 warps, 2m x 4n, warp tile 64x32).
// ===========================================================================
#define BKC 32
#define SSTR 36   // smem row stride in floats (4 mod 32 -> conflict-free frags)

__device__ __forceinline__ void mma_tf32(
    float& c0, float& c1, float& c2, float& c3,
    uint32_t a0, uint32_t a1, uint32_t a2, uint32_t a3,
    uint32_t b0, uint32_t b1)
{
    asm volatile(
        "mma.sync.aligned.m16n8k8.row.col.f32.tf32.tf32.f32 "
        "{%0,%1,%2,%3}, {%4,%5,%6,%7}, {%8,%9}, {%0,%1,%2,%3};"
        : "+f"(c0), "+f"(c1), "+f"(c2), "+f"(c3)
        : "r"(a0), "r"(a1), "r"(a2), "r"(a3), "r"(b0), "r"(b1));
}

__device__ __forceinline__ uint4 cvt4_tf32(float4 v) {
    uint4 t;
    asm("cvt.rn.tf32.f32 %0, %1;" : "=r"(t.x) : "f"(v.x));
    asm("cvt.rn.tf32.f32 %0, %1;" : "=r"(t.y) : "f"(v.y));
    asm("cvt.rn.tf32.f32 %0, %1;" : "=r"(t.z) : "f"(v.z));
    asm("cvt.rn.tf32.f32 %0, %1;" : "=r"(t.w) : "f"(v.w));
    return t;
}

__global__ __launch_bounds__(256) void gemm_tf32_kernel(
    const float* __restrict__ A, const float* __restrict__ Bt,
    float* __restrict__ C, int M, int N, int K)
{
    __shared__ float As[128 * SSTR];
    __shared__ float Bs[128 * SSTR];

    const int tid  = threadIdx.x;
    const int wid  = tid >> 5;
    const int lane = tid & 31;
    const int bx = blockIdx.x, by = blockIdx.y;
    const int wm = wid & 1;          // 0..1
    const int wn = wid >> 1;         // 0..3
    const int lg = lane >> 2;        // 0..7  (group)
    const int lt = lane & 3;         // 0..3  (thread-in-group)

    // per-thread global-load mapping: 4 float4 per tile
    const int lrow[4] = { (0*256+tid) >> 3, (1*256+tid) >> 3,
                          (2*256+tid) >> 3, (3*256+tid) >> 3 };
    const int lc4 = (tid & 7) << 2;  // float offset within 32-float row

    const float* Ab = A  + (size_t)(by * 128) * K;
    const float* Bb = Bt + (size_t)(bx * 128) * K;

    float acc[4][4][4];
    #pragma unroll
    for (int i = 0; i < 4; i++)
        #pragma unroll
        for (int j = 0; j < 4; j++)
            #pragma unroll
            for (int q = 0; q < 4; q++) acc[i][j][q] = 0.f;

    // prologue: tile 0 -> smem
    #pragma unroll
    for (int i = 0; i < 4; i++) {
        uint4 a = cvt4_tf32(*(const float4*)(Ab + (size_t)lrow[i] * K + lc4));
        uint4 b = cvt4_tf32(*(const float4*)(Bb + (size_t)lrow[i] * K + lc4));
        *(uint4*)&As[lrow[i] * SSTR + lc4] = a;
        *(uint4*)&Bs[lrow[i] * SSTR + lc4] = b;
    }
    __syncthreads();

    for (int k0 = 0; k0 < K; k0 += BKC) {
        // prefetch next tile into registers
        uint4 pa[4], pb[4];
        bool more = (k0 + BKC) < K;
        if (more) {
            #pragma unroll
            for (int i = 0; i < 4; i++) {
                pa[i] = cvt4_tf32(*(const float4*)(Ab + (size_t)lrow[i] * K + k0 + BKC + lc4));
                pb[i] = cvt4_tf32(*(const float4*)(Bb + (size_t)lrow[i] * K + k0 + BKC + lc4));
            }
        }

        // compute on current smem tile: 4 k-steps of 8
        #pragma unroll
        for (int ks = 0; ks < 4; ks++) {
            int kk = (ks << 3) + lt;
            uint32_t a[4][4];
            #pragma unroll
            for (int mi = 0; mi < 4; mi++) {
                int r = wm * 64 + mi * 16 + lg;
                a[mi][0] = __float_as_uint(As[r * SSTR + kk]);
                a[mi][1] = __float_as_uint(As[(r + 8) * SSTR + kk]);
                a[mi][2] = __float_as_uint(As[r * SSTR + kk + 4]);
                a[mi][3] = __float_as_uint(As[(r + 8) * SSTR + kk + 4]);
            }
            #pragma unroll
            for (int ni = 0; ni < 4; ni++) {
                int nr = wn * 32 + ni * 8 + lg;
                uint32_t b0 = __float_as_uint(Bs[nr * SSTR + kk]);
                uint32_t b1 = __float_as_uint(Bs[nr * SSTR + kk + 4]);
                #pragma unroll
                for (int mi = 0; mi < 4; mi++)
                    mma_tf32(acc[mi][ni][0], acc[mi][ni][1], acc[mi][ni][2], acc[mi][ni][3],
                             a[mi][0], a[mi][1], a[mi][2], a[mi][3], b0, b1);
            }
        }
        __syncthreads();
        if (more) {
            #pragma unroll
            for (int i = 0; i < 4; i++) {
                *(uint4*)&As[lrow[i] * SSTR + lc4] = pa[i];
                *(uint4*)&Bs[lrow[i] * SSTR + lc4] = pb[i];
            }
            __syncthreads();
        }
    }

    // epilogue
    #pragma unroll
    for (int mi = 0; mi < 4; mi++) {
        int row = by * 128 + wm * 64 + mi * 16 + lg;
        #pragma unroll
        for (int ni = 0; ni < 4; ni++) {
            int col = bx * 128 + wn * 32 + ni * 8 + (lt << 1);
            float2 lo = make_float2(acc[mi][ni][0], acc[mi][ni][1]);
            float2 hi = make_float2(acc[mi][ni][2], acc[mi][ni][3]);
            *(float2*)(C + (size_t)row * N + col)       = lo;
            *(float2*)(C + (size_t)(row + 8) * N + col) = hi;
        }
    }
}

// ===========================================================================
// L2-normalize q and k head-vectors in-place. One warp per 64-dim vector.
// ===========================================================================
__global__ __launch_bounds__(256) void l2norm_kernel(float* __restrict__ qkv)
{
    int warp = (blockIdx.x << 3) + (threadIdx.x >> 5);
    int lane = threadIdx.x & 31;
    int row  = warp >> 5;
    int rem  = warp & 31;
    float* base = qkv + (size_t)row * QKVW + (size_t)(rem >> 4) * INNER + (size_t)(rem & 15) * DHEAD;
    float x0 = base[lane];
    float x1 = base[lane + 32];
    float ss = x0*x0 + x1*x1;
    #pragma unroll
    for (int o = 16; o; o >>= 1) ss += __shfl_xor_sync(0xffffffffu, ss, o);
    float inv = 1.0f / fmaxf(sqrtf(ss), 1e-12f);
    base[lane]      = x0 * inv;
    base[lane + 32] = x1 * inv;
}

// ===========================================================================
// Flash-style causal attention, fp32 SIMT (unchanged, known-good)
// ===========================================================================
#define TPAD 68
#define ATT_SMEM_BYTES (4 * 64 * TPAD * 4)

__global__ __launch_bounds__(256) void attn_kernel(
    const float* __restrict__ qkv, float* __restrict__ oat)
{
    extern __shared__ float sm[];
    float* Qt = sm;
    float* Kt = sm + 64 * TPAD;
    float* Vs = sm + 2 * 64 * TPAD;
    float* Ss = sm + 3 * 64 * TPAD;

    int tid = threadIdx.x;
    int qt = blockIdx.x, h = blockIdx.y, bb = blockIdx.z;
    int row0 = qt * 64;
    size_t rowbase = (size_t)bb * NSEQ;

    int rg = tid >> 4, cg = tid & 15;
    int r0 = rg << 2, c0 = cg << 2;

    for (int e = tid; e < 64 * 16; e += 256) {
        int i  = e >> 4;
        int d0 = (e & 15) << 2;
        float4 q4 = *(const float4*)(qkv + (rowbase + row0 + i) * QKVW + h * DHEAD + d0);
        Qt[(d0 + 0) * TPAD + i] = q4.x;
        Qt[(d0 + 1) * TPAD + i] = q4.y;
        Qt[(d0 + 2) * TPAD + i] = q4.z;
        Qt[(d0 + 3) * TPAD + i] = q4.w;
    }

    float m[4], l[4], o[4][4];
    #pragma unroll
    for (int i = 0; i < 4; i++) {
        m[i] = -INFINITY; l[i] = 0.f;
        #pragma unroll
        for (int j = 0; j < 4; j++) o[i][j] = 0.f;
    }

    for (int jt = 0; jt <= qt; jt++) {
        int j0 = jt * 64;
        __syncthreads();
        for (int e = tid; e < 64 * 16; e += 256) {
            int i  = e >> 4;
            int d0 = (e & 15) << 2;
            const float* src = qkv + (rowbase + j0 + i) * QKVW + h * DHEAD + d0;
            float4 k4 = *(const float4*)(src + INNER);
            Kt[(d0 + 0) * TPAD + i] = k4.x;
            Kt[(d0 + 1) * TPAD + i] = k4.y;
            Kt[(d0 + 2) * TPAD + i] = k4.z;
            Kt[(d0 + 3) * TPAD + i] = k4.w;
            float4 v4 = *(const float4*)(src + 2 * INNER);
            *(float4*)&Vs[i * TPAD + d0] = v4;
        }
        __syncthreads();

        float acc[4][4];
        #pragma unroll
        for (int i = 0; i < 4; i++)
            #pragma unroll
            for (int j = 0; j < 4; j++) acc[i][j] = 0.f;

        #pragma unroll 16
        for (int d = 0; d < 64; d++) {
            float4 kv = *(const float4*)&Kt[d * TPAD + c0];
            float4 qv = *(const float4*)&Qt[d * TPAD + r0];
            acc[0][0] += qv.x*kv.x; acc[0][1] += qv.x*kv.y; acc[0][2] += qv.x*kv.z; acc[0][3] += qv.x*kv.w;
            acc[1][0] += qv.y*kv.x; acc[1][1] += qv.y*kv.y; acc[1][2] += qv.y*kv.z; acc[1][3] += qv.y*kv.w;
            acc[2][0] += qv.z*kv.x; acc[2][1] += qv.z*kv.y; acc[2][2] += qv.z*kv.z; acc[2][3] += qv.z*kv.w;
            acc[3][0] += qv.w*kv.x; acc[3][1] += qv.w*kv.y; acc[3][2] += qv.w*kv.z; acc[3][3] += qv.w*kv.w;
        }

        #pragma unroll
        for (int i = 0; i < 4; i++)
            #pragma unroll
            for (int j = 0; j < 4; j++) acc[i][j] *= ATT_SCALE;

        if (jt == qt) {
            #pragma unroll
            for (int i = 0; i < 4; i++)
                #pragma unroll
                for (int j = 0; j < 4; j++)
                    if (c0 + j > r0 + i) acc[i][j] = -INFINITY;
        }

        #pragma unroll
        for (int i = 0; i < 4; i++) {
            float mt = fmaxf(fmaxf(acc[i][0], acc[i][1]), fmaxf(acc[i][2], acc[i][3]));
            mt = fmaxf(mt, __shfl_xor_sync(0xffffffffu, mt, 1));
            mt = fmaxf(mt, __shfl_xor_sync(0xffffffffu, mt, 2));
            mt = fmaxf(mt, __shfl_xor_sync(0xffffffffu, mt, 4));
            mt = fmaxf(mt, __shfl_xor_sync(0xffffffffu, mt, 8));
            float mn = fmaxf(m[i], mt);
            float corr = __expf(m[i] - mn);
            m[i] = mn;
            l[i] *= corr;
            #pragma unroll
            for (int j = 0; j < 4; j++) o[i][j] *= corr;
            float4 p;
            p.x = __expf(acc[i][0] - mn);
            p.y = __expf(acc[i][1] - mn);
            p.z = __expf(acc[i][2] - mn);
            p.w = __expf(acc[i][3] - mn);
            float ls = p.x + p.y + p.z + p.w;
            *(float4*)&Ss[(r0 + i) * TPAD + c0] = p;
            ls += __shfl_xor_sync(0xffffffffu, ls, 1);
            ls += __shfl_xor_sync(0xffffffffu, ls, 2);
            ls += __shfl_xor_sync(0xffffffffu, ls, 4);
            ls += __shfl_xor_sync(0xffffffffu, ls, 8);
            l[i] += ls;
        }
        __syncwarp();

        #pragma unroll 8
        for (int kk = 0; kk < 64; kk++) {
            float4 vv = *(const float4*)&Vs[kk * TPAD + c0];
            float p0 = Ss[(r0 + 0) * TPAD + kk];
            float p1 = Ss[(r0 + 1) * TPAD + kk];
            float p2 = Ss[(r0 + 2) * TPAD + kk];
            float p3 = Ss[(r0 + 3) * TPAD + kk];
            o[0][0] += p0*vv.x; o[0][1] += p0*vv.y; o[0][2] += p0*vv.z; o[0][3] += p0*vv.w;
            o[1][0] += p1*vv.x; o[1][1] += p1*vv.y; o[1][2] += p1*vv.z; o[1][3] += p1*vv.w;
            o[2][0] += p2*vv.x; o[2][1] += p2*vv.y; o[2][2] += p2*vv.z; o[2][3] += p2*vv.w;
            o[3][0] += p3*vv.x; o[3][1] += p3*vv.y; o[3][2] += p3*vv.z; o[3][3] += p3*vv.w;
        }
    }

    #pragma unroll
    for (int i = 0; i < 4; i++) {
        float inv = 1.0f / l[i];
        float4 st;
        st.x = o[i][0] * inv; st.y = o[i][1] * inv;
        st.z = o[i][2] * inv; st.w = o[i][3] * inv;
        *(float4*)(oat + (rowbase + row0 + r0 + i) * INNER + h * DHEAD + c0) = st;
    }
}

// ===========================================================================
extern "C" void kernel_launch(void* const* d_in, const int* in_sizes, int n_in,
                              void* d_out, int out_size)
{
    const float* x    = (const float*)d_in[0];
    const float* lnw  = (const float*)d_in[1];
    const float* lnb  = (const float*)d_in[2];
    const float* Wqkv = (const float*)d_in[3];
    const float* Wout = (const float*)d_in[4];
    float* out = (float*)d_out;

    float *xn, *qkvp, *oat, *wqkvT, *woutT;
    cudaGetSymbolAddress((void**)&xn,    g_xn);
    cudaGetSymbolAddress((void**)&qkvp,  g_qkv);
    cudaGetSymbolAddress((void**)&oat,   g_oat);
    cudaGetSymbolAddress((void**)&wqkvT, g_wqkvT);
    cudaGetSymbolAddress((void**)&woutT, g_woutT);

    cudaFuncSetAttribute(attn_kernel, cudaFuncAttributeMaxDynamicSharedMemorySize, ATT_SMEM_BYTES);

    ln_kernel<<<ROWS, 256>>>(x, lnw, lnb, xn);

    transpose_kernel<<<dim3(QKVW / 32, DIM / 32), 256>>>(Wqkv, wqkvT, DIM, QKVW);
    transpose_kernel<<<dim3(INNER / 32, DIM / 32), 256>>>(Wout, woutT, DIM, INNER);

    gemm_tf32_kernel<<<dim3(QKVW / 128, ROWS / 128), 256>>>(
        xn, wqkvT, qkvp, ROWS, QKVW, DIM);

    l2norm_kernel<<<(ROWS * HEADS * 2) / 8, 256>>>(qkvp);

    attn_kernel<<<dim3(NSEQ / 64, HEADS, BATCH), 256, ATT_SMEM_BYTES>>>(qkvp, oat);

    gemm_tf32_kernel<<<dim3(INNER / 128, ROWS / 128), 256>>>(
        oat, woutT, out, ROWS, INNER, DIM);
}

// round 4
// speedup vs baseline: 2.5819x; 1.5811x over previous
#include <cuda_runtime.h>
#include <math.h>
#include <stdint.h>

#define BATCH 2
#define NSEQ  2048
#define DIM   1024
#define HEADS 16
#define DHEAD 64
#define INNER 1024
#define ROWS  (BATCH*NSEQ)   // 4096
#define QKVW  (3*INNER)      // 3072
#define ATT_SCALE 8.0f
#define LN_EPS 1e-5f

// Scratch (static device allocations — allowed)
__device__ float g_xn   [(size_t)ROWS * DIM  ];
__device__ float g_qkv  [(size_t)ROWS * QKVW ];
__device__ float g_oat  [(size_t)ROWS * INNER];
__device__ float g_wqkvT[(size_t)QKVW * DIM  ];
__device__ float g_woutT[(size_t)INNER * DIM ];

// ===========================================================================
// common helpers
// ===========================================================================
__device__ __forceinline__ void mma_tf32(
    float& c0, float& c1, float& c2, float& c3,
    uint32_t a0, uint32_t a1, uint32_t a2, uint32_t a3,
    uint32_t b0, uint32_t b1)
{
    asm volatile(
        "mma.sync.aligned.m16n8k8.row.col.f32.tf32.tf32.f32 "
        "{%0,%1,%2,%3}, {%4,%5,%6,%7}, {%8,%9}, {%0,%1,%2,%3};"
        : "+f"(c0), "+f"(c1), "+f"(c2), "+f"(c3)
        : "r"(a0), "r"(a1), "r"(a2), "r"(a3), "r"(b0), "r"(b1));
}
__device__ __forceinline__ uint32_t cvt_tf32(float v) {
    uint32_t t;
    asm("cvt.rn.tf32.f32 %0, %1;" : "=r"(t) : "f"(v));
    return t;
}
__device__ __forceinline__ uint4 cvt4_tf32(float4 v) {
    uint4 t;
    t.x = cvt_tf32(v.x); t.y = cvt_tf32(v.y);
    t.z = cvt_tf32(v.z); t.w = cvt_tf32(v.w);
    return t;
}

// ===========================================================================
// LayerNorm: one block (256 thr) per row of 1024
// ===========================================================================
__global__ __launch_bounds__(256) void ln_kernel(
    const float* __restrict__ x, const float* __restrict__ w,
    const float* __restrict__ b, float* __restrict__ out)
{
    int row = blockIdx.x;
    int tid = threadIdx.x;
    const float4 v = ((const float4*)(x + (size_t)row * DIM))[tid];
    float s  = v.x + v.y + v.z + v.w;
    float ss = v.x*v.x + v.y*v.y + v.z*v.z + v.w*v.w;
    #pragma unroll
    for (int o = 16; o; o >>= 1) {
        s  += __shfl_xor_sync(0xffffffffu, s,  o);
        ss += __shfl_xor_sync(0xffffffffu, ss, o);
    }
    __shared__ float sh_s[8], sh_ss[8];
    int wid = tid >> 5, lane = tid & 31;
    if (lane == 0) { sh_s[wid] = s; sh_ss[wid] = ss; }
    __syncthreads();
    if (tid == 0) {
        float a = 0.f, q = 0.f;
        #pragma unroll
        for (int i = 0; i < 8; i++) { a += sh_s[i]; q += sh_ss[i]; }
        sh_s[0] = a; sh_ss[0] = q;
    }
    __syncthreads();
    float mu   = sh_s[0]  * (1.0f / DIM);
    float var  = sh_ss[0] * (1.0f / DIM) - mu * mu;
    float rstd = rsqrtf(var + LN_EPS);
    float4 w4 = ((const float4*)w)[tid];
    float4 b4 = ((const float4*)b)[tid];
    float4 o4;
    o4.x = (v.x - mu) * rstd * w4.x + b4.x;
    o4.y = (v.y - mu) * rstd * w4.y + b4.y;
    o4.z = (v.z - mu) * rstd * w4.z + b4.z;
    o4.w = (v.w - mu) * rstd * w4.w + b4.w;
    ((float4*)(out + (size_t)row * DIM))[tid] = o4;
}

// ===========================================================================
// 32x32 smem transpose: out[c*R + r] = in[r*C + c]
// ===========================================================================
__global__ __launch_bounds__(256) void transpose_kernel(
    const float* __restrict__ in, float* __restrict__ out, int R, int C)
{
    __shared__ float t[32][33];
    int c0 = blockIdx.x << 5, r0 = blockIdx.y << 5;
    int tx = threadIdx.x & 31, ty = threadIdx.x >> 5;
    #pragma unroll
    for (int i = 0; i < 4; i++) {
        int r = ty + i * 8;
        t[r][tx] = in[(size_t)(r0 + r) * C + c0 + tx];
    }
    __syncthreads();
    #pragma unroll
    for (int i = 0; i < 4; i++) {
        int r = ty + i * 8;
        out[(size_t)(c0 + r) * R + r0 + tx] = t[tx][r];
    }
}

// ===========================================================================
// tf32 mma.sync GEMM: C[M,N] = A[M,K] @ Bt[N,K]^T (unchanged from R3, passing)
// ===========================================================================
#define BKC 32
#define SSTR 36

__global__ __launch_bounds__(256) void gemm_tf32_kernel(
    const float* __restrict__ A, const float* __restrict__ Bt,
    float* __restrict__ C, int M, int N, int K)
{
    __shared__ float As[128 * SSTR];
    __shared__ float Bs[128 * SSTR];

    const int tid  = threadIdx.x;
    const int wid  = tid >> 5;
    const int lane = tid & 31;
    const int bx = blockIdx.x, by = blockIdx.y;
    const int wm = wid & 1;
    const int wn = wid >> 1;
    const int lg = lane >> 2;
    const int lt = lane & 3;

    const int lrow[4] = { (0*256+tid) >> 3, (1*256+tid) >> 3,
                          (2*256+tid) >> 3, (3*256+tid) >> 3 };
    const int lc4 = (tid & 7) << 2;

    const float* Ab = A  + (size_t)(by * 128) * K;
    const float* Bb = Bt + (size_t)(bx * 128) * K;

    float acc[4][4][4];
    #pragma unroll
    for (int i = 0; i < 4; i++)
        #pragma unroll
        for (int j = 0; j < 4; j++)
            #pragma unroll
            for (int q = 0; q < 4; q++) acc[i][j][q] = 0.f;

    #pragma unroll
    for (int i = 0; i < 4; i++) {
        uint4 a = cvt4_tf32(*(const float4*)(Ab + (size_t)lrow[i] * K + lc4));
        uint4 b = cvt4_tf32(*(const float4*)(Bb + (size_t)lrow[i] * K + lc4));
        *(uint4*)&As[lrow[i] * SSTR + lc4] = a;
        *(uint4*)&Bs[lrow[i] * SSTR + lc4] = b;
    }
    __syncthreads();

    for (int k0 = 0; k0 < K; k0 += BKC) {
        uint4 pa[4], pb[4];
        bool more = (k0 + BKC) < K;
        if (more) {
            #pragma unroll
            for (int i = 0; i < 4; i++) {
                pa[i] = cvt4_tf32(*(const float4*)(Ab + (size_t)lrow[i] * K + k0 + BKC + lc4));
                pb[i] = cvt4_tf32(*(const float4*)(Bb + (size_t)lrow[i] * K + k0 + BKC + lc4));
            }
        }

        #pragma unroll
        for (int ks = 0; ks < 4; ks++) {
            int kk = (ks << 3) + lt;
            uint32_t a[4][4];
            #pragma unroll
            for (int mi = 0; mi < 4; mi++) {
                int r = wm * 64 + mi * 16 + lg;
                a[mi][0] = __float_as_uint(As[r * SSTR + kk]);
                a[mi][1] = __float_as_uint(As[(r + 8) * SSTR + kk]);
                a[mi][2] = __float_as_uint(As[r * SSTR + kk + 4]);
                a[mi][3] = __float_as_uint(As[(r + 8) * SSTR + kk + 4]);
            }
            #pragma unroll
            for (int ni = 0; ni < 4; ni++) {
                int nr = wn * 32 + ni * 8 + lg;
                uint32_t b0 = __float_as_uint(Bs[nr * SSTR + kk]);
                uint32_t b1 = __float_as_uint(Bs[nr * SSTR + kk + 4]);
                #pragma unroll
                for (int mi = 0; mi < 4; mi++)
                    mma_tf32(acc[mi][ni][0], acc[mi][ni][1], acc[mi][ni][2], acc[mi][ni][3],
                             a[mi][0], a[mi][1], a[mi][2], a[mi][3], b0, b1);
            }
        }
        __syncthreads();
        if (more) {
            #pragma unroll
            for (int i = 0; i < 4; i++) {
                *(uint4*)&As[lrow[i] * SSTR + lc4] = pa[i];
                *(uint4*)&Bs[lrow[i] * SSTR + lc4] = pb[i];
            }
            __syncthreads();
        }
    }

    #pragma unroll
    for (int mi = 0; mi < 4; mi++) {
        int row = by * 128 + wm * 64 + mi * 16 + lg;
        #pragma unroll
        for (int ni = 0; ni < 4; ni++) {
            int col = bx * 128 + wn * 32 + ni * 8 + (lt << 1);
            float2 lo = make_float2(acc[mi][ni][0], acc[mi][ni][1]);
            float2 hi = make_float2(acc[mi][ni][2], acc[mi][ni][3]);
            *(float2*)(C + (size_t)row * N + col)       = lo;
            *(float2*)(C + (size_t)(row + 8) * N + col) = hi;
        }
    }
}

// ===========================================================================
// L2-normalize q and k head-vectors in-place. One warp per 64-dim vector.
// ===========================================================================
__global__ __launch_bounds__(256) void l2norm_kernel(float* __restrict__ qkv)
{
    int warp = (blockIdx.x << 3) + (threadIdx.x >> 5);
    int lane = threadIdx.x & 31;
    int row  = warp >> 5;
    int rem  = warp & 31;
    float* base = qkv + (size_t)row * QKVW + (size_t)(rem >> 4) * INNER + (size_t)(rem & 15) * DHEAD;
    float x0 = base[lane];
    float x1 = base[lane + 32];
    float ss = x0*x0 + x1*x1;
    #pragma unroll
    for (int o = 16; o; o >>= 1) ss += __shfl_xor_sync(0xffffffffu, ss, o);
    float inv = 1.0f / fmaxf(sqrtf(ss), 1e-12f);
    base[lane]      = x0 * inv;
    base[lane + 32] = x1 * inv;
}

// ===========================================================================
// Tensor-core flash attention (tf32 mma.sync)
// CTA: 64 q rows, 128 threads (4 warps x 16 rows). Key tiles of 64. d = 64.
// Smem: Ks[64 key][68] (d inner), Vt[64 d][68] (key inner), Ps[64 row][68].
// ===========================================================================
#define PSTR 68
#define ATT2_SMEM ((64 + 64 + 64) * PSTR * 4)

__global__ __launch_bounds__(128) void attn_tc_kernel(
    const float* __restrict__ qkv, float* __restrict__ oat)
{
    extern __shared__ float sm[];
    float* Ks = sm;                 // [key][d]   (B operand for scores)
    float* Vt = sm + 64 * PSTR;     // [d][key]   (B operand for PV)
    float* Ps = sm + 128 * PSTR;    // [row][key] (A operand for PV)

    const int tid  = threadIdx.x;
    const int w    = tid >> 5;
    const int lane = tid & 31;
    const int lg = lane >> 2, lt = lane & 3;
    const int qtIdx = gridDim.x - 1 - blockIdx.x;   // long CTAs launch first
    const int h = blockIdx.y, bb = blockIdx.z;
    const int row0 = qtIdx * 64;
    const size_t rowbase = (size_t)bb * NSEQ;
    const int R0 = row0 + w * 16;                   // warp's first q row

    // --- Q fragments (prescaled by ATT_SCALE, tf32), resident all kernel ---
    uint32_t aq[8][4];
    {
        const float* q0 = qkv + (rowbase + R0 + lg) * QKVW + h * DHEAD;
        const float* q1 = q0 + 8 * QKVW;
        #pragma unroll
        for (int ks = 0; ks < 8; ks++) {
            int c = ks * 8 + lt;
            aq[ks][0] = cvt_tf32(q0[c]     * ATT_SCALE);
            aq[ks][1] = cvt_tf32(q1[c]     * ATT_SCALE);
            aq[ks][2] = cvt_tf32(q0[c + 4] * ATT_SCALE);
            aq[ks][3] = cvt_tf32(q1[c + 4] * ATT_SCALE);
        }
    }

    float oacc[8][4];
    #pragma unroll
    for (int ni = 0; ni < 8; ni++)
        #pragma unroll
        for (int q = 0; q < 4; q++) oacc[ni][q] = 0.f;
    float m0 = -INFINITY, m1 = -INFINITY, l0 = 0.f, l1 = 0.f;

    const int ntiles = qtIdx + 1;
    for (int jt = 0; jt < ntiles; jt++) {
        const int j0 = jt * 64;
        __syncthreads();   // previous tile's smem reads done

        // --- cooperative load: K -> Ks[key][d], V -> Vt[d][key], tf32 ---
        #pragma unroll
        for (int rep = 0; rep < 8; rep++) {
            int e  = rep * 128 + tid;     // 0..1023
            int i  = e >> 4;              // key 0..63
            int d0 = (e & 15) << 2;       // d 0..60
            const float* src = qkv + (rowbase + j0 + i) * QKVW + h * DHEAD + d0;
            uint4 kt = cvt4_tf32(*(const float4*)(src + INNER));
            *(uint4*)&Ks[i * PSTR + d0] = kt;
            uint4 vt = cvt4_tf32(*(const float4*)(src + 2 * INNER));
            Vt[(d0 + 0) * PSTR + i] = __uint_as_float(vt.x);
            Vt[(d0 + 1) * PSTR + i] = __uint_as_float(vt.y);
            Vt[(d0 + 2) * PSTR + i] = __uint_as_float(vt.z);
            Vt[(d0 + 3) * PSTR + i] = __uint_as_float(vt.w);
        }
        __syncthreads();

        // --- scores: sacc[ni] = (8*Q) . K^T  (16 rows x 64 keys per warp) ---
        float sacc[8][4];
        #pragma unroll
        for (int ni = 0; ni < 8; ni++)
            #pragma unroll
            for (int q = 0; q < 4; q++) sacc[ni][q] = 0.f;

        #pragma unroll
        for (int ks = 0; ks < 8; ks++) {
            int kk = ks * 8 + lt;
            #pragma unroll
            for (int ni = 0; ni < 8; ni++) {
                int key = ni * 8 + lg;
                uint32_t b0 = __float_as_uint(Ks[key * PSTR + kk]);
                uint32_t b1 = __float_as_uint(Ks[key * PSTR + kk + 4]);
                mma_tf32(sacc[ni][0], sacc[ni][1], sacc[ni][2], sacc[ni][3],
                         aq[ks][0], aq[ks][1], aq[ks][2], aq[ks][3], b0, b1);
            }
        }

        // --- causal mask (only the diagonal tile needs it) ---
        if (j0 + 63 > R0) {
            int ra = R0 + lg, rb = ra + 8;
            #pragma unroll
            for (int ni = 0; ni < 8; ni++) {
                int k0c = j0 + ni * 8 + 2 * lt;
                if (k0c     > ra) sacc[ni][0] = -INFINITY;
                if (k0c + 1 > ra) sacc[ni][1] = -INFINITY;
                if (k0c     > rb) sacc[ni][2] = -INFINITY;
                if (k0c + 1 > rb) sacc[ni][3] = -INFINITY;
            }
        }

        // --- online softmax (rows lg and lg+8) ---
        float mt0 = -INFINITY, mt1 = -INFINITY;
        #pragma unroll
        for (int ni = 0; ni < 8; ni++) {
            mt0 = fmaxf(mt0, fmaxf(sacc[ni][0], sacc[ni][1]));
            mt1 = fmaxf(mt1, fmaxf(sacc[ni][2], sacc[ni][3]));
        }
        mt0 = fmaxf(mt0, __shfl_xor_sync(0xffffffffu, mt0, 1));
        mt0 = fmaxf(mt0, __shfl_xor_sync(0xffffffffu, mt0, 2));
        mt1 = fmaxf(mt1, __shfl_xor_sync(0xffffffffu, mt1, 1));
        mt1 = fmaxf(mt1, __shfl_xor_sync(0xffffffffu, mt1, 2));
        float mn0 = fmaxf(m0, mt0), mn1 = fmaxf(m1, mt1);
        float c0f = __expf(m0 - mn0), c1f = __expf(m1 - mn1);
        m0 = mn0; m1 = mn1;

        float s0 = 0.f, s1 = 0.f;
        int rowa = w * 16 + lg;
        #pragma unroll
        for (int ni = 0; ni < 8; ni++) {
            uint32_t p0 = cvt_tf32(__expf(sacc[ni][0] - m0));
            uint32_t p1 = cvt_tf32(__expf(sacc[ni][1] - m0));
            uint32_t p2 = cvt_tf32(__expf(sacc[ni][2] - m1));
            uint32_t p3 = cvt_tf32(__expf(sacc[ni][3] - m1));
            s0 += __uint_as_float(p0) + __uint_as_float(p1);
            s1 += __uint_as_float(p2) + __uint_as_float(p3);
            int col = ni * 8 + 2 * lt;
            *(uint2*)&Ps[rowa * PSTR + col]       = make_uint2(p0, p1);
            *(uint2*)&Ps[(rowa + 8) * PSTR + col] = make_uint2(p2, p3);
        }
        s0 += __shfl_xor_sync(0xffffffffu, s0, 1);
        s0 += __shfl_xor_sync(0xffffffffu, s0, 2);
        s1 += __shfl_xor_sync(0xffffffffu, s1, 1);
        s1 += __shfl_xor_sync(0xffffffffu, s1, 2);
        l0 = l0 * c0f + s0;
        l1 = l1 * c1f + s1;
        #pragma unroll
        for (int ni = 0; ni < 8; ni++) {
            oacc[ni][0] *= c0f; oacc[ni][1] *= c0f;
            oacc[ni][2] *= c1f; oacc[ni][3] *= c1f;
        }
        __syncwarp();

        // --- PV: oacc += P @ V  (A from Ps, B from Vt) ---
        #pragma unroll
        for (int kc = 0; kc < 8; kc++) {
            int kk = kc * 8 + lt;
            uint32_t a0 = __float_as_uint(Ps[rowa * PSTR + kk]);
            uint32_t a1 = __float_as_uint(Ps[(rowa + 8) * PSTR + kk]);
            uint32_t a2 = __float_as_uint(Ps[rowa * PSTR + kk + 4]);
            uint32_t a3 = __float_as_uint(Ps[(rowa + 8) * PSTR + kk + 4]);
            #pragma unroll
            for (int ni = 0; ni < 8; ni++) {
                int dr = ni * 8 + lg;
                uint32_t b0 = __float_as_uint(Vt[dr * PSTR + kk]);
                uint32_t b1 = __float_as_uint(Vt[dr * PSTR + kk + 4]);
                mma_tf32(oacc[ni][0], oacc[ni][1], oacc[ni][2], oacc[ni][3],
                         a0, a1, a2, a3, b0, b1);
            }
        }
    }

    // --- epilogue: normalize and write [b, n, h*d] ---
    float il0 = 1.0f / l0, il1 = 1.0f / l1;
    float* outa = oat + (rowbase + R0 + lg) * INNER + h * DHEAD;
    float* outb = outa + 8 * INNER;
    #pragma unroll
    for (int ni = 0; ni < 8; ni++) {
        int col = ni * 8 + 2 * lt;
        *(float2*)(outa + col) = make_float2(oacc[ni][0] * il0, oacc[ni][1] * il0);
        *(float2*)(outb + col) = make_float2(oacc[ni][2] * il1, oacc[ni][3] * il1);
    }
}

// ===========================================================================
extern "C" void kernel_launch(void* const* d_in, const int* in_sizes, int n_in,
                              void* d_out, int out_size)
{
    const float* x    = (const float*)d_in[0];
    const float* lnw  = (const float*)d_in[1];
    const float* lnb  = (const float*)d_in[2];
    const float* Wqkv = (const float*)d_in[3];
    const float* Wout = (const float*)d_in[4];
    float* out = (float*)d_out;

    float *xn, *qkvp, *oat, *wqkvT, *woutT;
    cudaGetSymbolAddress((void**)&xn,    g_xn);
    cudaGetSymbolAddress((void**)&qkvp,  g_qkv);
    cudaGetSymbolAddress((void**)&oat,   g_oat);
    cudaGetSymbolAddress((void**)&wqkvT, g_wqkvT);
    cudaGetSymbolAddress((void**)&woutT, g_woutT);

    cudaFuncSetAttribute(attn_tc_kernel, cudaFuncAttributeMaxDynamicSharedMemorySize, ATT2_SMEM);

    ln_kernel<<<ROWS, 256>>>(x, lnw, lnb, xn);

    transpose_kernel<<<dim3(QKVW / 32, DIM / 32), 256>>>(Wqkv, wqkvT, DIM, QKVW);
    transpose_kernel<<<dim3(INNER / 32, DIM / 32), 256>>>(Wout, woutT, DIM, INNER);

    gemm_tf32_kernel<<<dim3(QKVW / 128, ROWS / 128), 256>>>(
        xn, wqkvT, qkvp, ROWS, QKVW, DIM);

    l2norm_kernel<<<(ROWS * HEADS * 2) / 8, 256>>>(qkvp);

    attn_tc_kernel<<<dim3(NSEQ / 64, HEADS, BATCH), 128, ATT2_SMEM>>>(qkvp, oat);

    gemm_tf32_kernel<<<dim3(INNER / 128, ROWS / 128), 256>>>(
        oat, woutT, out, ROWS, INNER, DIM);
}

// round 5
// speedup vs baseline: 3.1004x; 1.2008x over previous
#include <cuda_runtime.h>
#include <math.h>
#include <stdint.h>

#define BATCH 2
#define NSEQ  2048
#define DIM   1024
#define HEADS 16
#define DHEAD 64
#define INNER 1024
#define ROWS  (BATCH*NSEQ)   // 4096
#define QKVW  (3*INNER)      // 3072
#define ATT_SCALE 8.0f
#define LN_EPS 1e-5f

// Scratch (static device allocations — allowed)
__device__ float g_xn   [(size_t)ROWS * DIM  ];
__device__ float g_qkv  [(size_t)ROWS * QKVW ];
__device__ float g_oat  [(size_t)ROWS * INNER];
__device__ float g_wqkvT[(size_t)QKVW * DIM  ];
__device__ float g_woutT[(size_t)INNER * DIM ];

// ===========================================================================
// common helpers
// ===========================================================================
__device__ __forceinline__ void mma_tf32(
    float& c0, float& c1, float& c2, float& c3,
    uint32_t a0, uint32_t a1, uint32_t a2, uint32_t a3,
    uint32_t b0, uint32_t b1)
{
    asm volatile(
        "mma.sync.aligned.m16n8k8.row.col.f32.tf32.tf32.f32 "
        "{%0,%1,%2,%3}, {%4,%5,%6,%7}, {%8,%9}, {%0,%1,%2,%3};"
        : "+f"(c0), "+f"(c1), "+f"(c2), "+f"(c3)
        : "r"(a0), "r"(a1), "r"(a2), "r"(a3), "r"(b0), "r"(b1));
}
__device__ __forceinline__ uint32_t cvt_tf32(float v) {
    uint32_t t;
    asm("cvt.rn.tf32.f32 %0, %1;" : "=r"(t) : "f"(v));
    return t;
}
__device__ __forceinline__ float cvt_tf32f(float v) {
    return __uint_as_float(cvt_tf32(v));
}
__device__ __forceinline__ uint4 cvt4_tf32(float4 v) {
    uint4 t;
    t.x = cvt_tf32(v.x); t.y = cvt_tf32(v.y);
    t.z = cvt_tf32(v.z); t.w = cvt_tf32(v.w);
    return t;
}
__device__ __forceinline__ void cp_async16(uint32_t dst, const void* src) {
    asm volatile("cp.async.cg.shared.global [%0], [%1], 16;" :: "r"(dst), "l"(src));
}
__device__ __forceinline__ void cp_commit() {
    asm volatile("cp.async.commit_group;" ::: "memory");
}
__device__ __forceinline__ void cp_wait0() {
    asm volatile("cp.async.wait_group 0;" ::: "memory");
}

// ===========================================================================
// LayerNorm: one block (256 thr) per row of 1024. Output rounded to tf32
// (consumed only by the tf32 GEMM — identical values to load-time cvt).
// ===========================================================================
__global__ __launch_bounds__(256) void ln_kernel(
    const float* __restrict__ x, const float* __restrict__ w,
    const float* __restrict__ b, float* __restrict__ out)
{
    int row = blockIdx.x;
    int tid = threadIdx.x;
    const float4 v = ((const float4*)(x + (size_t)row * DIM))[tid];
    float s  = v.x + v.y + v.z + v.w;
    float ss = v.x*v.x + v.y*v.y + v.z*v.z + v.w*v.w;
    #pragma unroll
    for (int o = 16; o; o >>= 1) {
        s  += __shfl_xor_sync(0xffffffffu, s,  o);
        ss += __shfl_xor_sync(0xffffffffu, ss, o);
    }
    __shared__ float sh_s[8], sh_ss[8];
    int wid = tid >> 5, lane = tid & 31;
    if (lane == 0) { sh_s[wid] = s; sh_ss[wid] = ss; }
    __syncthreads();
    if (tid == 0) {
        float a = 0.f, q = 0.f;
        #pragma unroll
        for (int i = 0; i < 8; i++) { a += sh_s[i]; q += sh_ss[i]; }
        sh_s[0] = a; sh_ss[0] = q;
    }
    __syncthreads();
    float mu   = sh_s[0]  * (1.0f / DIM);
    float var  = sh_ss[0] * (1.0f / DIM) - mu * mu;
    float rstd = rsqrtf(var + LN_EPS);
    float4 w4 = ((const float4*)w)[tid];
    float4 b4 = ((const float4*)b)[tid];
    float4 o4;
    o4.x = cvt_tf32f((v.x - mu) * rstd * w4.x + b4.x);
    o4.y = cvt_tf32f((v.y - mu) * rstd * w4.y + b4.y);
    o4.z = cvt_tf32f((v.z - mu) * rstd * w4.z + b4.z);
    o4.w = cvt_tf32f((v.w - mu) * rstd * w4.w + b4.w);
    ((float4*)(out + (size_t)row * DIM))[tid] = o4;
}

// ===========================================================================
// 32x32 smem transpose, output rounded to tf32 (weights feed tf32 GEMM only)
// ===========================================================================
__global__ __launch_bounds__(256) void transpose_kernel(
    const float* __restrict__ in, float* __restrict__ out, int R, int C)
{
    __shared__ float t[32][33];
    int c0 = blockIdx.x << 5, r0 = blockIdx.y << 5;
    int tx = threadIdx.x & 31, ty = threadIdx.x >> 5;
    #pragma unroll
    for (int i = 0; i < 4; i++) {
        int r = ty + i * 8;
        t[r][tx] = in[(size_t)(r0 + r) * C + c0 + tx];
    }
    __syncthreads();
    #pragma unroll
    for (int i = 0; i < 4; i++) {
        int r = ty + i * 8;
        out[(size_t)(c0 + r) * R + r0 + tx] = cvt_tf32f(t[tx][r]);
    }
}

// ===========================================================================
// tf32 mma.sync GEMM v2: C[M,N] = A[M,K] @ Bt[N,K]^T
// A, Bt pre-rounded to tf32 by producers. cp.async 2-stage pipeline.
// CTA tile 128x128, BK=32, 256 threads (8 warps 2m x 4n), 2 CTAs/SM.
// ===========================================================================
#define BKC 32
#define SSTR 36

__global__ __launch_bounds__(256, 2) void gemm_tf32_kernel(
    const float* __restrict__ A, const float* __restrict__ Bt,
    float* __restrict__ C, int M, int N, int K)
{
    __shared__ float As[2][128 * SSTR];
    __shared__ float Bs[2][128 * SSTR];

    const int tid  = threadIdx.x;
    const int wid  = tid >> 5;
    const int lane = tid & 31;
    const int bx = blockIdx.x, by = blockIdx.y;
    const int wm = wid & 1;
    const int wn = wid >> 1;
    const int lg = lane >> 2;
    const int lt = lane & 3;

    const int lr0 = tid >> 3;            // rows: lr0, lr0+32, +64, +96
    const int lc4 = (tid & 7) << 2;

    const float* Ab = A  + (size_t)(by * 128) * K;
    const float* Bb = Bt + (size_t)(bx * 128) * K;

    uint32_t sA[2], sB[2];
    sA[0] = (uint32_t)__cvta_generic_to_shared(&As[0][0]);
    sA[1] = (uint32_t)__cvta_generic_to_shared(&As[1][0]);
    sB[0] = (uint32_t)__cvta_generic_to_shared(&Bs[0][0]);
    sB[1] = (uint32_t)__cvta_generic_to_shared(&Bs[1][0]);

    float acc[4][4][4];
    #pragma unroll
    for (int i = 0; i < 4; i++)
        #pragma unroll
        for (int j = 0; j < 4; j++)
            #pragma unroll
            for (int q = 0; q < 4; q++) acc[i][j][q] = 0.f;

    const int NC = K / BKC;

    // prologue: chunk 0 -> slot 0
    #pragma unroll
    for (int i = 0; i < 4; i++) {
        int r = lr0 + i * 32;
        cp_async16(sA[0] + (uint32_t)(r * SSTR + lc4) * 4, Ab + (size_t)r * K + lc4);
        cp_async16(sB[0] + (uint32_t)(r * SSTR + lc4) * 4, Bb + (size_t)r * K + lc4);
    }
    cp_commit();

    for (int c = 0; c < NC; c++) {
        cp_wait0();
        __syncthreads();

        if (c + 1 < NC) {
            int slot = (c + 1) & 1;
            int koff = (c + 1) * BKC + lc4;
            #pragma unroll
            for (int i = 0; i < 4; i++) {
                int r = lr0 + i * 32;
                cp_async16(sA[slot] + (uint32_t)(r * SSTR + lc4) * 4, Ab + (size_t)r * K + koff);
                cp_async16(sB[slot] + (uint32_t)(r * SSTR + lc4) * 4, Bb + (size_t)r * K + koff);
            }
            cp_commit();
        }

        const float* Ac = As[c & 1];
        const float* Bc = Bs[c & 1];
        #pragma unroll
        for (int ks = 0; ks < 4; ks++) {
            int kk = (ks << 3) + lt;
            uint32_t a[4][4];
            #pragma unroll
            for (int mi = 0; mi < 4; mi++) {
                int r = wm * 64 + mi * 16 + lg;
                a[mi][0] = __float_as_uint(Ac[r * SSTR + kk]);
                a[mi][1] = __float_as_uint(Ac[(r + 8) * SSTR + kk]);
                a[mi][2] = __float_as_uint(Ac[r * SSTR + kk + 4]);
                a[mi][3] = __float_as_uint(Ac[(r + 8) * SSTR + kk + 4]);
            }
            #pragma unroll
            for (int ni = 0; ni < 4; ni++) {
                int nr = wn * 32 + ni * 8 + lg;
                uint32_t b0 = __float_as_uint(Bc[nr * SSTR + kk]);
                uint32_t b1 = __float_as_uint(Bc[nr * SSTR + kk + 4]);
                #pragma unroll
                for (int mi = 0; mi < 4; mi++)
                    mma_tf32(acc[mi][ni][0], acc[mi][ni][1], acc[mi][ni][2], acc[mi][ni][3],
                             a[mi][0], a[mi][1], a[mi][2], a[mi][3], b0, b1);
            }
        }
    }

    // epilogue
    #pragma unroll
    for (int mi = 0; mi < 4; mi++) {
        int row = by * 128 + wm * 64 + mi * 16 + lg;
        #pragma unroll
        for (int ni = 0; ni < 4; ni++) {
            int col = bx * 128 + wn * 32 + ni * 8 + (lt << 1);
            float2 lo = make_float2(acc[mi][ni][0], acc[mi][ni][1]);
            float2 hi = make_float2(acc[mi][ni][2], acc[mi][ni][3]);
            *(float2*)(C + (size_t)row * N + col)       = lo;
            *(float2*)(C + (size_t)(row + 8) * N + col) = hi;
        }
    }
}

// ===========================================================================
// L2-normalize q and k head-vectors in-place. One warp per 64-dim vector.
// ===========================================================================
__global__ __launch_bounds__(256) void l2norm_kernel(float* __restrict__ qkv)
{
    int warp = (blockIdx.x << 3) + (threadIdx.x >> 5);
    int lane = threadIdx.x & 31;
    int row  = warp >> 5;
    int rem  = warp & 31;
    float* base = qkv + (size_t)row * QKVW + (size_t)(rem >> 4) * INNER + (size_t)(rem & 15) * DHEAD;
    float x0 = base[lane];
    float x1 = base[lane + 32];
    float ss = x0*x0 + x1*x1;
    #pragma unroll
    for (int o = 16; o; o >>= 1) ss += __shfl_xor_sync(0xffffffffu, ss, o);
    float inv = 1.0f / fmaxf(sqrtf(ss), 1e-12f);
    base[lane]      = x0 * inv;
    base[lane + 32] = x1 * inv;
}

// ===========================================================================
// Tensor-core flash attention (tf32 mma.sync) — unchanged from R4 except
// epilogue rounds output to tf32 (feeds tf32 GEMM; identical values).
// ===========================================================================
#define PSTR 68
#define ATT2_SMEM ((64 + 64 + 64) * PSTR * 4)

__global__ __launch_bounds__(128) void attn_tc_kernel(
    const float* __restrict__ qkv, float* __restrict__ oat)
{
    extern __shared__ float sm[];
    float* Ks = sm;                 // [key][d]   (B operand for scores)
    float* Vt = sm + 64 * PSTR;     // [d][key]   (B operand for PV)
    float* Ps = sm + 128 * PSTR;    // [row][key] (A operand for PV)

    const int tid  = threadIdx.x;
    const int w    = tid >> 5;
    const int lane = tid & 31;
    const int lg = lane >> 2, lt = lane & 3;
    const int qtIdx = gridDim.x - 1 - blockIdx.x;
    const int h = blockIdx.y, bb = blockIdx.z;
    const int row0 = qtIdx * 64;
    const size_t rowbase = (size_t)bb * NSEQ;
    const int R0 = row0 + w * 16;

    uint32_t aq[8][4];
    {
        const float* q0 = qkv + (rowbase + R0 + lg) * QKVW + h * DHEAD;
        const float* q1 = q0 + 8 * QKVW;
        #pragma unroll
        for (int ks = 0; ks < 8; ks++) {
            int c = ks * 8 + lt;
            aq[ks][0] = cvt_tf32(q0[c]     * ATT_SCALE);
            aq[ks][1] = cvt_tf32(q1[c]     * ATT_SCALE);
            aq[ks][2] = cvt_tf32(q0[c + 4] * ATT_SCALE);
            aq[ks][3] = cvt_tf32(q1[c + 4] * ATT_SCALE);
        }
    }

    float oacc[8][4];
    #pragma unroll
    for (int ni = 0; ni < 8; ni++)
        #pragma unroll
        for (int q = 0; q < 4; q++) oacc[ni][q] = 0.f;
    float m0 = -INFINITY, m1 = -INFINITY, l0 = 0.f, l1 = 0.f;

    const int ntiles = qtIdx + 1;
    for (int jt = 0; jt < ntiles; jt++) {
        const int j0 = jt * 64;
        __syncthreads();

        #pragma unroll
        for (int rep = 0; rep < 8; rep++) {
            int e  = rep * 128 + tid;
            int i  = e >> 4;
            int d0 = (e & 15) << 2;
            const float* src = qkv + (rowbase + j0 + i) * QKVW + h * DHEAD + d0;
            uint4 kt = cvt4_tf32(*(const float4*)(src + INNER));
            *(uint4*)&Ks[i * PSTR + d0] = kt;
            uint4 vt = cvt4_tf32(*(const float4*)(src + 2 * INNER));
            Vt[(d0 + 0) * PSTR + i] = __uint_as_float(vt.x);
            Vt[(d0 + 1) * PSTR + i] = __uint_as_float(vt.y);
            Vt[(d0 + 2) * PSTR + i] = __uint_as_float(vt.z);
            Vt[(d0 + 3) * PSTR + i] = __uint_as_float(vt.w);
        }
        __syncthreads();

        float sacc[8][4];
        #pragma unroll
        for (int ni = 0; ni < 8; ni++)
            #pragma unroll
            for (int q = 0; q < 4; q++) sacc[ni][q] = 0.f;

        #pragma unroll
        for (int ks = 0; ks < 8; ks++) {
            int kk = ks * 8 + lt;
            #pragma unroll
            for (int ni = 0; ni < 8; ni++) {
                int key = ni * 8 + lg;
                uint32_t b0 = __float_as_uint(Ks[key * PSTR + kk]);
                uint32_t b1 = __float_as_uint(Ks[key * PSTR + kk + 4]);
                mma_tf32(sacc[ni][0], sacc[ni][1], sacc[ni][2], sacc[ni][3],
                         aq[ks][0], aq[ks][1], aq[ks][2], aq[ks][3], b0, b1);
            }
        }

        if (j0 + 63 > R0) {
            int ra = R0 + lg, rb = ra + 8;
            #pragma unroll
            for (int ni = 0; ni < 8; ni++) {
                int k0c = j0 + ni * 8 + 2 * lt;
                if (k0c     > ra) sacc[ni][0] = -INFINITY;
                if (k0c + 1 > ra) sacc[ni][1] = -INFINITY;
                if (k0c     > rb) sacc[ni][2] = -INFINITY;
                if (k0c + 1 > rb) sacc[ni][3] = -INFINITY;
            }
        }

        float mt0 = -INFINITY, mt1 = -INFINITY;
        #pragma unroll
        for (int ni = 0; ni < 8; ni++) {
            mt0 = fmaxf(mt0, fmaxf(sacc[ni][0], sacc[ni][1]));
            mt1 = fmaxf(mt1, fmaxf(sacc[ni][2], sacc[ni][3]));
        }
        mt0 = fmaxf(mt0, __shfl_xor_sync(0xffffffffu, mt0, 1));
        mt0 = fmaxf(mt0, __shfl_xor_sync(0xffffffffu, mt0, 2));
        mt1 = fmaxf(mt1, __shfl_xor_sync(0xffffffffu, mt1, 1));
        mt1 = fmaxf(mt1, __shfl_xor_sync(0xffffffffu, mt1, 2));
        float mn0 = fmaxf(m0, mt0), mn1 = fmaxf(m1, mt1);
        float c0f = __expf(m0 - mn0), c1f = __expf(m1 - mn1);
        m0 = mn0; m1 = mn1;

        float s0 = 0.f, s1 = 0.f;
        int rowa = w * 16 + lg;
        #pragma unroll
        for (int ni = 0; ni < 8; ni++) {
            uint32_t p0 = cvt_tf32(__expf(sacc[ni][0] - m0));
            uint32_t p1 = cvt_tf32(__expf(sacc[ni][1] - m0));
            uint32_t p2 = cvt_tf32(__expf(sacc[ni][2] - m1));
            uint32_t p3 = cvt_tf32(__expf(sacc[ni][3] - m1));
            s0 += __uint_as_float(p0) + __uint_as_float(p1);
            s1 += __uint_as_float(p2) + __uint_as_float(p3);
            int col = ni * 8 + 2 * lt;
            *(uint2*)&Ps[rowa * PSTR + col]       = make_uint2(p0, p1);
            *(uint2*)&Ps[(rowa + 8) * PSTR + col] = make_uint2(p2, p3);
        }
        s0 += __shfl_xor_sync(0xffffffffu, s0, 1);
        s0 += __shfl_xor_sync(0xffffffffu, s0, 2);
        s1 += __shfl_xor_sync(0xffffffffu, s1, 1);
        s1 += __shfl_xor_sync(0xffffffffu, s1, 2);
        l0 = l0 * c0f + s0;
        l1 = l1 * c1f + s1;
        #pragma unroll
        for (int ni = 0; ni < 8; ni++) {
            oacc[ni][0] *= c0f; oacc[ni][1] *= c0f;
            oacc[ni][2] *= c1f; oacc[ni][3] *= c1f;
        }
        __syncwarp();

        #pragma unroll
        for (int kc = 0; kc < 8; kc++) {
            int kk = kc * 8 + lt;
            uint32_t a0 = __float_as_uint(Ps[rowa * PSTR + kk]);
            uint32_t a1 = __float_as_uint(Ps[(rowa + 8) * PSTR + kk]);
            uint32_t a2 = __float_as_uint(Ps[rowa * PSTR + kk + 4]);
            uint32_t a3 = __float_as_uint(Ps[(rowa + 8) * PSTR + kk + 4]);
            #pragma unroll
            for (int ni = 0; ni < 8; ni++) {
                int dr = ni * 8 + lg;
                uint32_t b0 = __float_as_uint(Vt[dr * PSTR + kk]);
                uint32_t b1 = __float_as_uint(Vt[dr * PSTR + kk + 4]);
                mma_tf32(oacc[ni][0], oacc[ni][1], oacc[ni][2], oacc[ni][3],
                         a0, a1, a2, a3, b0, b1);
            }
        }
    }

    float il0 = 1.0f / l0, il1 = 1.0f / l1;
    float* outa = oat + (rowbase + R0 + lg) * INNER + h * DHEAD;
    float* outb = outa + 8 * INNER;
    #pragma unroll
    for (int ni = 0; ni < 8; ni++) {
        int col = ni * 8 + 2 * lt;
        *(float2*)(outa + col) = make_float2(cvt_tf32f(oacc[ni][0] * il0), cvt_tf32f(oacc[ni][1] * il0));
        *(float2*)(outb + col) = make_float2(cvt_tf32f(oacc[ni][2] * il1), cvt_tf32f(oacc[ni][3] * il1));
    }
}

// ===========================================================================
extern "C" void kernel_launch(void* const* d_in, const int* in_sizes, int n_in,
                              void* d_out, int out_size)
{
    const float* x    = (const float*)d_in[0];
    const float* lnw  = (const float*)d_in[1];
    const float* lnb  = (const float*)d_in[2];
    const float* Wqkv = (const float*)d_in[3];
    const float* Wout = (const float*)d_in[4];
    float* out = (float*)d_out;

    float *xn, *qkvp, *oat, *wqkvT, *woutT;
    cudaGetSymbolAddress((void**)&xn,    g_xn);
    cudaGetSymbolAddress((void**)&qkvp,  g_qkv);
    cudaGetSymbolAddress((void**)&oat,   g_oat);
    cudaGetSymbolAddress((void**)&wqkvT, g_wqkvT);
    cudaGetSymbolAddress((void**)&woutT, g_woutT);

    cudaFuncSetAttribute(attn_tc_kernel, cudaFuncAttributeMaxDynamicSharedMemorySize, ATT2_SMEM);

    ln_kernel<<<ROWS, 256>>>(x, lnw, lnb, xn);

    transpose_kernel<<<dim3(QKVW / 32, DIM / 32), 256>>>(Wqkv, wqkvT, DIM, QKVW);
    transpose_kernel<<<dim3(INNER / 32, DIM / 32), 256>>>(Wout, woutT, DIM, INNER);

    gemm_tf32_kernel<<<dim3(QKVW / 128, ROWS / 128), 256>>>(
        xn, wqkvT, qkvp, ROWS, QKVW, DIM);

    l2norm_kernel<<<(ROWS * HEADS * 2) / 8, 256>>>(qkvp);

    attn_tc_kernel<<<dim3(NSEQ / 64, HEADS, BATCH), 128, ATT2_SMEM>>>(qkvp, oat);

    gemm_tf32_kernel<<<dim3(INNER / 128, ROWS / 128), 256>>>(
        oat, woutT, out, ROWS, INNER, DIM);
}

// round 6
// speedup vs baseline: 3.3096x; 1.0675x over previous
#include <cuda_runtime.h>
#include <math.h>
#include <stdint.h>

#define BATCH 2
#define NSEQ  2048
#define DIM   1024
#define HEADS 16
#define DHEAD 64
#define INNER 1024
#define ROWS  (BATCH*NSEQ)   // 4096
#define QKVW  (3*INNER)      // 3072
#define ATT_SCALE 8.0f
#define LN_EPS 1e-5f

// Scratch (static device allocations — allowed)
__device__ float g_xn   [(size_t)ROWS * DIM  ];
__device__ float g_qkv  [(size_t)ROWS * QKVW ];
__device__ float g_oat  [(size_t)ROWS * INNER];
__device__ float g_wqkvT[(size_t)QKVW * DIM  ];
__device__ float g_woutT[(size_t)INNER * DIM ];

// ===========================================================================
// common helpers
// ===========================================================================
__device__ __forceinline__ void mma_tf32(
    float& c0, float& c1, float& c2, float& c3,
    uint32_t a0, uint32_t a1, uint32_t a2, uint32_t a3,
    uint32_t b0, uint32_t b1)
{
    asm volatile(
        "mma.sync.aligned.m16n8k8.row.col.f32.tf32.tf32.f32 "
        "{%0,%1,%2,%3}, {%4,%5,%6,%7}, {%8,%9}, {%0,%1,%2,%3};"
        : "+f"(c0), "+f"(c1), "+f"(c2), "+f"(c3)
        : "r"(a0), "r"(a1), "r"(a2), "r"(a3), "r"(b0), "r"(b1));
}
__device__ __forceinline__ uint32_t cvt_tf32(float v) {
    uint32_t t;
    asm("cvt.rn.tf32.f32 %0, %1;" : "=r"(t) : "f"(v));
    return t;
}
__device__ __forceinline__ float cvt_tf32f(float v) {
    return __uint_as_float(cvt_tf32(v));
}
__device__ __forceinline__ uint4 cvt4_tf32(float4 v) {
    uint4 t;
    t.x = cvt_tf32(v.x); t.y = cvt_tf32(v.y);
    t.z = cvt_tf32(v.z); t.w = cvt_tf32(v.w);
    return t;
}
__device__ __forceinline__ void cp_async16(uint32_t dst, const void* src) {
    asm volatile("cp.async.cg.shared.global [%0], [%1], 16;" :: "r"(dst), "l"(src));
}
__device__ __forceinline__ void cp_commit() {
    asm volatile("cp.async.commit_group;" ::: "memory");
}
__device__ __forceinline__ void cp_wait0() {
    asm volatile("cp.async.wait_group 0;" ::: "memory");
}

// ===========================================================================
// LayerNorm: one block (256 thr) per row of 1024. Output rounded to tf32.
// ===========================================================================
__global__ __launch_bounds__(256) void ln_kernel(
    const float* __restrict__ x, const float* __restrict__ w,
    const float* __restrict__ b, float* __restrict__ out)
{
    int row = blockIdx.x;
    int tid = threadIdx.x;
    const float4 v = ((const float4*)(x + (size_t)row * DIM))[tid];
    float s  = v.x + v.y + v.z + v.w;
    float ss = v.x*v.x + v.y*v.y + v.z*v.z + v.w*v.w;
    #pragma unroll
    for (int o = 16; o; o >>= 1) {
        s  += __shfl_xor_sync(0xffffffffu, s,  o);
        ss += __shfl_xor_sync(0xffffffffu, ss, o);
    }
    __shared__ float sh_s[8], sh_ss[8];
    int wid = tid >> 5, lane = tid & 31;
    if (lane == 0) { sh_s[wid] = s; sh_ss[wid] = ss; }
    __syncthreads();
    if (tid == 0) {
        float a = 0.f, q = 0.f;
        #pragma unroll
        for (int i = 0; i < 8; i++) { a += sh_s[i]; q += sh_ss[i]; }
        sh_s[0] = a; sh_ss[0] = q;
    }
    __syncthreads();
    float mu   = sh_s[0]  * (1.0f / DIM);
    float var  = sh_ss[0] * (1.0f / DIM) - mu * mu;
    float rstd = rsqrtf(var + LN_EPS);
    float4 w4 = ((const float4*)w)[tid];
    float4 b4 = ((const float4*)b)[tid];
    float4 o4;
    o4.x = cvt_tf32f((v.x - mu) * rstd * w4.x + b4.x);
    o4.y = cvt_tf32f((v.y - mu) * rstd * w4.y + b4.y);
    o4.z = cvt_tf32f((v.z - mu) * rstd * w4.z + b4.z);
    o4.w = cvt_tf32f((v.w - mu) * rstd * w4.w + b4.w);
    ((float4*)(out + (size_t)row * DIM))[tid] = o4;
}

// ===========================================================================
// 32x32 smem transpose, output rounded to tf32
// ===========================================================================
__global__ __launch_bounds__(256) void transpose_kernel(
    const float* __restrict__ in, float* __restrict__ out, int R, int C)
{
    __shared__ float t[32][33];
    int c0 = blockIdx.x << 5, r0 = blockIdx.y << 5;
    int tx = threadIdx.x & 31, ty = threadIdx.x >> 5;
    #pragma unroll
    for (int i = 0; i < 4; i++) {
        int r = ty + i * 8;
        t[r][tx] = in[(size_t)(r0 + r) * C + c0 + tx];
    }
    __syncthreads();
    #pragma unroll
    for (int i = 0; i < 4; i++) {
        int r = ty + i * 8;
        out[(size_t)(c0 + r) * R + r0 + tx] = cvt_tf32f(t[tx][r]);
    }
}

// ===========================================================================
// tf32 mma.sync GEMM (unchanged from R5, passing)
// ===========================================================================
#define BKC 32
#define SSTR 36

__global__ __launch_bounds__(256, 2) void gemm_tf32_kernel(
    const float* __restrict__ A, const float* __restrict__ Bt,
    float* __restrict__ C, int M, int N, int K)
{
    __shared__ float As[2][128 * SSTR];
    __shared__ float Bs[2][128 * SSTR];

    const int tid  = threadIdx.x;
    const int wid  = tid >> 5;
    const int lane = tid & 31;
    const int bx = blockIdx.x, by = blockIdx.y;
    const int wm = wid & 1;
    const int wn = wid >> 1;
    const int lg = lane >> 2;
    const int lt = lane & 3;

    const int lr0 = tid >> 3;
    const int lc4 = (tid & 7) << 2;

    const float* Ab = A  + (size_t)(by * 128) * K;
    const float* Bb = Bt + (size_t)(bx * 128) * K;

    uint32_t sA[2], sB[2];
    sA[0] = (uint32_t)__cvta_generic_to_shared(&As[0][0]);
    sA[1] = (uint32_t)__cvta_generic_to_shared(&As[1][0]);
    sB[0] = (uint32_t)__cvta_generic_to_shared(&Bs[0][0]);
    sB[1] = (uint32_t)__cvta_generic_to_shared(&Bs[1][0]);

    float acc[4][4][4];
    #pragma unroll
    for (int i = 0; i < 4; i++)
        #pragma unroll
        for (int j = 0; j < 4; j++)
            #pragma unroll
            for (int q = 0; q < 4; q++) acc[i][j][q] = 0.f;

    const int NC = K / BKC;

    #pragma unroll
    for (int i = 0; i < 4; i++) {
        int r = lr0 + i * 32;
        cp_async16(sA[0] + (uint32_t)(r * SSTR + lc4) * 4, Ab + (size_t)r * K + lc4);
        cp_async16(sB[0] + (uint32_t)(r * SSTR + lc4) * 4, Bb + (size_t)r * K + lc4);
    }
    cp_commit();

    for (int c = 0; c < NC; c++) {
        cp_wait0();
        __syncthreads();

        if (c + 1 < NC) {
            int slot = (c + 1) & 1;
            int koff = (c + 1) * BKC + lc4;
            #pragma unroll
            for (int i = 0; i < 4; i++) {
                int r = lr0 + i * 32;
                cp_async16(sA[slot] + (uint32_t)(r * SSTR + lc4) * 4, Ab + (size_t)r * K + koff);
                cp_async16(sB[slot] + (uint32_t)(r * SSTR + lc4) * 4, Bb + (size_t)r * K + koff);
            }
            cp_commit();
        }

        const float* Ac = As[c & 1];
        const float* Bc = Bs[c & 1];
        #pragma unroll
        for (int ks = 0; ks < 4; ks++) {
            int kk = (ks << 3) + lt;
            uint32_t a[4][4];
            #pragma unroll
            for (int mi = 0; mi < 4; mi++) {
                int r = wm * 64 + mi * 16 + lg;
                a[mi][0] = __float_as_uint(Ac[r * SSTR + kk]);
                a[mi][1] = __float_as_uint(Ac[(r + 8) * SSTR + kk]);
                a[mi][2] = __float_as_uint(Ac[r * SSTR + kk + 4]);
                a[mi][3] = __float_as_uint(Ac[(r + 8) * SSTR + kk + 4]);
            }
            #pragma unroll
            for (int ni = 0; ni < 4; ni++) {
                int nr = wn * 32 + ni * 8 + lg;
                uint32_t b0 = __float_as_uint(Bc[nr * SSTR + kk]);
                uint32_t b1 = __float_as_uint(Bc[nr * SSTR + kk + 4]);
                #pragma unroll
                for (int mi = 0; mi < 4; mi++)
                    mma_tf32(acc[mi][ni][0], acc[mi][ni][1], acc[mi][ni][2], acc[mi][ni][3],
                             a[mi][0], a[mi][1], a[mi][2], a[mi][3], b0, b1);
            }
        }
    }

    #pragma unroll
    for (int mi = 0; mi < 4; mi++) {
        int row = by * 128 + wm * 64 + mi * 16 + lg;
        #pragma unroll
        for (int ni = 0; ni < 4; ni++) {
            int col = bx * 128 + wn * 32 + ni * 8 + (lt << 1);
            float2 lo = make_float2(acc[mi][ni][0], acc[mi][ni][1]);
            float2 hi = make_float2(acc[mi][ni][2], acc[mi][ni][3]);
            *(float2*)(C + (size_t)row * N + col)       = lo;
            *(float2*)(C + (size_t)(row + 8) * N + col) = hi;
        }
    }
}

// ===========================================================================
// L2-normalize q and k head-vectors in-place. K is additionally rounded to
// tf32 (it is consumed only by the tf32 attention mma via raw cp.async copy).
// ===========================================================================
__global__ __launch_bounds__(256) void l2norm_kernel(float* __restrict__ qkv)
{
    int warp = (blockIdx.x << 3) + (threadIdx.x >> 5);
    int lane = threadIdx.x & 31;
    int row  = warp >> 5;
    int rem  = warp & 31;
    bool is_k = (rem & 16) != 0;
    float* base = qkv + (size_t)row * QKVW + (size_t)(rem >> 4) * INNER + (size_t)(rem & 15) * DHEAD;
    float x0 = base[lane];
    float x1 = base[lane + 32];
    float ss = x0*x0 + x1*x1;
    #pragma unroll
    for (int o = 16; o; o >>= 1) ss += __shfl_xor_sync(0xffffffffu, ss, o);
    float inv = 1.0f / fmaxf(sqrtf(ss), 1e-12f);
    float y0 = x0 * inv, y1 = x1 * inv;
    if (is_k) { y0 = cvt_tf32f(y0); y1 = cvt_tf32f(y1); }
    base[lane]      = y0;
    base[lane + 32] = y1;
}

// ===========================================================================
// Tensor-core flash attention v3 (tf32 mma.sync)
// CTA: 128 q rows, 256 threads (8 warps x 16 rows). Key tiles of 64.
// Smem: Ks[64 key][68] (cp.async, K pre-rounded), Vt[64 d][68], Ps[128][68].
// ===========================================================================
#define PSTR 68
#define ATT3_SMEM ((64 + 64 + 128) * PSTR * 4)   // 69632 B

__global__ __launch_bounds__(256) void attn_tc_kernel(
    const float* __restrict__ qkv, float* __restrict__ oat)
{
    extern __shared__ float sm[];
    float* Ks = sm;                 // [key][d]   (B operand for scores)
    float* Vt = sm + 64 * PSTR;     // [d][key]   (B operand for PV)
    float* Ps = sm + 128 * PSTR;    // [row][key] (A operand for PV)

    const int tid  = threadIdx.x;
    const int w    = tid >> 5;
    const int lane = tid & 31;
    const int lg = lane >> 2, lt = lane & 3;
    const int qtIdx = gridDim.x - 1 - blockIdx.x;   // long CTAs first
    const int h = blockIdx.y, bb = blockIdx.z;
    const int row0 = qtIdx * 128;
    const size_t rowbase = (size_t)bb * NSEQ;
    const int R0 = row0 + w * 16;                   // warp's first q row

    const uint32_t ksAddr = (uint32_t)__cvta_generic_to_shared(Ks);

    // --- Q fragments (prescaled by ATT_SCALE, tf32), resident all kernel ---
    uint32_t aq[8][4];
    {
        const float* q0 = qkv + (rowbase + R0 + lg) * QKVW + h * DHEAD;
        const float* q1 = q0 + 8 * QKVW;
        #pragma unroll
        for (int ks = 0; ks < 8; ks++) {
            int c = ks * 8 + lt;
            aq[ks][0] = cvt_tf32(q0[c]     * ATT_SCALE);
            aq[ks][1] = cvt_tf32(q1[c]     * ATT_SCALE);
            aq[ks][2] = cvt_tf32(q0[c + 4] * ATT_SCALE);
            aq[ks][3] = cvt_tf32(q1[c + 4] * ATT_SCALE);
        }
    }

    float oacc[8][4];
    #pragma unroll
    for (int ni = 0; ni < 8; ni++)
        #pragma unroll
        for (int q = 0; q < 4; q++) oacc[ni][q] = 0.f;
    float m0 = -INFINITY, m1 = -INFINITY, l0 = 0.f, l1 = 0.f;

    const int ntiles = 2 * qtIdx + 2;
    for (int jt = 0; jt < ntiles; jt++) {
        const int j0 = jt * 64;
        __syncthreads();   // previous tile's smem reads done

        // --- K tile via cp.async (K pre-rounded to tf32 in l2norm) ---
        #pragma unroll
        for (int rep = 0; rep < 4; rep++) {
            int e  = rep * 256 + tid;     // 0..1023
            int i  = e >> 4;              // key 0..63
            int d0 = (e & 15) << 2;       // d 0..60
            cp_async16(ksAddr + (uint32_t)(i * PSTR + d0) * 4,
                       qkv + (rowbase + j0 + i) * QKVW + INNER + h * DHEAD + d0);
        }
        cp_commit();

        // --- V tile: load + tf32 + transpose while K copy is in flight ---
        #pragma unroll
        for (int rep = 0; rep < 4; rep++) {
            int e  = rep * 256 + tid;
            int i  = e >> 4;
            int d0 = (e & 15) << 2;
            const float* src = qkv + (rowbase + j0 + i) * QKVW + 2 * INNER + h * DHEAD + d0;
            uint4 vt = cvt4_tf32(*(const float4*)src);
            Vt[(d0 + 0) * PSTR + i] = __uint_as_float(vt.x);
            Vt[(d0 + 1) * PSTR + i] = __uint_as_float(vt.y);
            Vt[(d0 + 2) * PSTR + i] = __uint_as_float(vt.z);
            Vt[(d0 + 3) * PSTR + i] = __uint_as_float(vt.w);
        }
        cp_wait0();
        __syncthreads();

        // warps whose rows all precede this key tile are fully masked: skip
        if (j0 > R0 + 15) continue;

        // --- scores ---
        float sacc[8][4];
        #pragma unroll
        for (int ni = 0; ni < 8; ni++)
            #pragma unroll
            for (int q = 0; q < 4; q++) sacc[ni][q] = 0.f;

        #pragma unroll
        for (int ks = 0; ks < 8; ks++) {
            int kk = ks * 8 + lt;
            #pragma unroll
            for (int ni = 0; ni < 8; ni++) {
                int key = ni * 8 + lg;
                uint32_t b0 = __float_as_uint(Ks[key * PSTR + kk]);
                uint32_t b1 = __float_as_uint(Ks[key * PSTR + kk + 4]);
                mma_tf32(sacc[ni][0], sacc[ni][1], sacc[ni][2], sacc[ni][3],
                         aq[ks][0], aq[ks][1], aq[ks][2], aq[ks][3], b0, b1);
            }
        }

        // --- causal mask (diagonal-crossing tiles only) ---
        if (j0 + 63 > R0) {
            int ra = R0 + lg, rb = ra + 8;
            #pragma unroll
            for (int ni = 0; ni < 8; ni++) {
                int k0c = j0 + ni * 8 + 2 * lt;
                if (k0c     > ra) sacc[ni][0] = -INFINITY;
                if (k0c + 1 > ra) sacc[ni][1] = -INFINITY;
                if (k0c     > rb) sacc[ni][2] = -INFINITY;
                if (k0c + 1 > rb) sacc[ni][3] = -INFINITY;
            }
        }

        // --- online softmax (rows lg and lg+8) ---
        float mt0 = -INFINITY, mt1 = -INFINITY;
        #pragma unroll
        for (int ni = 0; ni < 8; ni++) {
            mt0 = fmaxf(mt0, fmaxf(sacc[ni][0], sacc[ni][1]));
            mt1 = fmaxf(mt1, fmaxf(sacc[ni][2], sacc[ni][3]));
        }
        mt0 = fmaxf(mt0, __shfl_xor_sync(0xffffffffu, mt0, 1));
        mt0 = fmaxf(mt0, __shfl_xor_sync(0xffffffffu, mt0, 2));
        mt1 = fmaxf(mt1, __shfl_xor_sync(0xffffffffu, mt1, 1));
        mt1 = fmaxf(mt1, __shfl_xor_sync(0xffffffffu, mt1, 2));
        float mn0 = fmaxf(m0, mt0), mn1 = fmaxf(m1, mt1);
        float c0f = __expf(m0 - mn0), c1f = __expf(m1 - mn1);
        m0 = mn0; m1 = mn1;

        float s0 = 0.f, s1 = 0.f;
        int rowa = w * 16 + lg;
        #pragma unroll
        for (int ni = 0; ni < 8; ni++) {
            uint32_t p0 = cvt_tf32(__expf(sacc[ni][0] - m0));
            uint32_t p1 = cvt_tf32(__expf(sacc[ni][1] - m0));
            uint32_t p2 = cvt_tf32(__expf(sacc[ni][2] - m1));
            uint32_t p3 = cvt_tf32(__expf(sacc[ni][3] - m1));
            s0 += __uint_as_float(p0) + __uint_as_float(p1);
            s1 += __uint_as_float(p2) + __uint_as_float(p3);
            int col = ni * 8 + 2 * lt;
            *(uint2*)&Ps[rowa * PSTR + col]       = make_uint2(p0, p1);
            *(uint2*)&Ps[(rowa + 8) * PSTR + col] = make_uint2(p2, p3);
        }
        s0 += __shfl_xor_sync(0xffffffffu, s0, 1);
        s0 += __shfl_xor_sync(0xffffffffu, s0, 2);
        s1 += __shfl_xor_sync(0xffffffffu, s1, 1);
        s1 += __shfl_xor_sync(0xffffffffu, s1, 2);
        l0 = l0 * c0f + s0;
        l1 = l1 * c1f + s1;
        #pragma unroll
        for (int ni = 0; ni < 8; ni++) {
            oacc[ni][0] *= c0f; oacc[ni][1] *= c0f;
            oacc[ni][2] *= c1f; oacc[ni][3] *= c1f;
        }
        __syncwarp();

        // --- PV: oacc += P @ V ---
        #pragma unroll
        for (int kc = 0; kc < 8; kc++) {
            int kk = kc * 8 + lt;
            uint32_t a0 = __float_as_uint(Ps[rowa * PSTR + kk]);
            uint32_t a1 = __float_as_uint(Ps[(rowa + 8) * PSTR + kk]);
            uint32_t a2 = __float_as_uint(Ps[rowa * PSTR + kk + 4]);
            uint32_t a3 = __float_as_uint(Ps[(rowa + 8) * PSTR + kk + 4]);
            #pragma unroll
            for (int ni = 0; ni < 8; ni++) {
                int dr = ni * 8 + lg;
                uint32_t b0 = __float_as_uint(Vt[dr * PSTR + kk]);
                uint32_t b1 = __float_as_uint(Vt[dr * PSTR + kk + 4]);
                mma_tf32(oacc[ni][0], oacc[ni][1], oacc[ni][2], oacc[ni][3],
                         a0, a1, a2, a3, b0, b1);
            }
        }
    }

    // --- epilogue: normalize, round to tf32 (feeds tf32 out-proj), write ---
    float il0 = 1.0f / l0, il1 = 1.0f / l1;
    float* outa = oat + (rowbase + R0 + lg) * INNER + h * DHEAD;
    float* outb = outa + 8 * INNER;
    #pragma unroll
    for (int ni = 0; ni < 8; ni++) {
        int col = ni * 8 + 2 * lt;
        *(float2*)(outa + col) = make_float2(cvt_tf32f(oacc[ni][0] * il0), cvt_tf32f(oacc[ni][1] * il0));
        *(float2*)(outb + col) = make_float2(cvt_tf32f(oacc[ni][2] * il1), cvt_tf32f(oacc[ni][3] * il1));
    }
}

// ===========================================================================
extern "C" void kernel_launch(void* const* d_in, const int* in_sizes, int n_in,
                              void* d_out, int out_size)
{
    const float* x    = (const float*)d_in[0];
    const float* lnw  = (const float*)d_in[1];
    const float* lnb  = (const float*)d_in[2];
    const float* Wqkv = (const float*)d_in[3];
    const float* Wout = (const float*)d_in[4];
    float* out = (float*)d_out;

    float *xn, *qkvp, *oat, *wqkvT, *woutT;
    cudaGetSymbolAddress((void**)&xn,    g_xn);
    cudaGetSymbolAddress((void**)&qkvp,  g_qkv);
    cudaGetSymbolAddress((void**)&oat,   g_oat);
    cudaGetSymbolAddress((void**)&wqkvT, g_wqkvT);
    cudaGetSymbolAddress((void**)&woutT, g_woutT);

    cudaFuncSetAttribute(attn_tc_kernel, cudaFuncAttributeMaxDynamicSharedMemorySize, ATT3_SMEM);

    ln_kernel<<<ROWS, 256>>>(x, lnw, lnb, xn);

    transpose_kernel<<<dim3(QKVW / 32, DIM / 32), 256>>>(Wqkv, wqkvT, DIM, QKVW);
    transpose_kernel<<<dim3(INNER / 32, DIM / 32), 256>>>(Wout, woutT, DIM, INNER);

    gemm_tf32_kernel<<<dim3(QKVW / 128, ROWS / 128), 256>>>(
        xn, wqkvT, qkvp, ROWS, QKVW, DIM);

    l2norm_kernel<<<(ROWS * HEADS * 2) / 8, 256>>>(qkvp);

    attn_tc_kernel<<<dim3(NSEQ / 128, HEADS, BATCH), 256, ATT3_SMEM>>>(qkvp, oat);

    gemm_tf32_kernel<<<dim3(INNER / 128, ROWS / 128), 256>>>(
        oat, woutT, out, ROWS, INNER, DIM);
}

// round 7
// speedup vs baseline: 4.8428x; 1.4633x over previous
#include <cuda_runtime.h>
#include <cuda_fp16.h>
#include <math.h>
#include <stdint.h>

#define BATCH 2
#define NSEQ  2048
#define DIM   1024
#define HEADS 16
#define DHEAD 64
#define INNER 1024
#define ROWS  (BATCH*NSEQ)   // 4096
#define QKVW  (3*INNER)      // 3072
#define ATT_SCALE 8.0f
#define LN_EPS 1e-5f

// Scratch (static device allocations — allowed)
__device__ __half g_xn_h  [(size_t)ROWS * DIM  ];
__device__ float  g_qkv   [(size_t)ROWS * QKVW ];
__device__ __half g_oat_h [(size_t)ROWS * INNER];
__device__ __half g_wqkvT [(size_t)QKVW * DIM  ];
__device__ __half g_woutT [(size_t)INNER * DIM ];

// ===========================================================================
// helpers
// ===========================================================================
__device__ __forceinline__ void mma_f16(
    float& c0, float& c1, float& c2, float& c3,
    uint32_t a0, uint32_t a1, uint32_t a2, uint32_t a3,
    uint32_t b0, uint32_t b1)
{
    asm volatile(
        "mma.sync.aligned.m16n8k16.row.col.f32.f16.f16.f32 "
        "{%0,%1,%2,%3}, {%4,%5,%6,%7}, {%8,%9}, {%0,%1,%2,%3};"
        : "+f"(c0), "+f"(c1), "+f"(c2), "+f"(c3)
        : "r"(a0), "r"(a1), "r"(a2), "r"(a3), "r"(b0), "r"(b1));
}
__device__ __forceinline__ uint32_t pack_h2(float a, float b) {
    __half2 h = __floats2half2_rn(a, b);
    return *(uint32_t*)&h;
}
__device__ __forceinline__ void cp_async16(uint32_t dst, const void* src) {
    asm volatile("cp.async.cg.shared.global [%0], [%1], 16;" :: "r"(dst), "l"(src));
}
__device__ __forceinline__ void cp_commit() {
    asm volatile("cp.async.commit_group;" ::: "memory");
}
__device__ __forceinline__ void cp_wait0() {
    asm volatile("cp.async.wait_group 0;" ::: "memory");
}

// ===========================================================================
// LayerNorm: one block (256 thr) per row of 1024. Output in fp16.
// ===========================================================================
__global__ __launch_bounds__(256) void ln_kernel(
    const float* __restrict__ x, const float* __restrict__ w,
    const float* __restrict__ b, __half* __restrict__ out)
{
    int row = blockIdx.x;
    int tid = threadIdx.x;
    const float4 v = ((const float4*)(x + (size_t)row * DIM))[tid];
    float s  = v.x + v.y + v.z + v.w;
    float ss = v.x*v.x + v.y*v.y + v.z*v.z + v.w*v.w;
    #pragma unroll
    for (int o = 16; o; o >>= 1) {
        s  += __shfl_xor_sync(0xffffffffu, s,  o);
        ss += __shfl_xor_sync(0xffffffffu, ss, o);
    }
    __shared__ float sh_s[8], sh_ss[8];
    int wid = tid >> 5, lane = tid & 31;
    if (lane == 0) { sh_s[wid] = s; sh_ss[wid] = ss; }
    __syncthreads();
    if (tid == 0) {
        float a = 0.f, q = 0.f;
        #pragma unroll
        for (int i = 0; i < 8; i++) { a += sh_s[i]; q += sh_ss[i]; }
        sh_s[0] = a; sh_ss[0] = q;
    }
    __syncthreads();
    float mu   = sh_s[0]  * (1.0f / DIM);
    float var  = sh_ss[0] * (1.0f / DIM) - mu * mu;
    float rstd = rsqrtf(var + LN_EPS);
    float4 w4 = ((const float4*)w)[tid];
    float4 b4 = ((const float4*)b)[tid];
    uint2 o2;
    o2.x = pack_h2((v.x - mu) * rstd * w4.x + b4.x,
                   (v.y - mu) * rstd * w4.y + b4.y);
    o2.y = pack_h2((v.z - mu) * rstd * w4.z + b4.z,
                   (v.w - mu) * rstd * w4.w + b4.w);
    ((uint2*)(out + (size_t)row * DIM))[tid] = o2;
}

// ===========================================================================
// 32x32 smem transpose, fp32 in -> fp16 out
// ===========================================================================
__global__ __launch_bounds__(256) void transpose_kernel(
    const float* __restrict__ in, __half* __restrict__ out, int R, int C)
{
    __shared__ float t[32][33];
    int c0 = blockIdx.x << 5, r0 = blockIdx.y << 5;
    int tx = threadIdx.x & 31, ty = threadIdx.x >> 5;
    #pragma unroll
    for (int i = 0; i < 4; i++) {
        int r = ty + i * 8;
        t[r][tx] = in[(size_t)(r0 + r) * C + c0 + tx];
    }
    __syncthreads();
    #pragma unroll
    for (int i = 0; i < 4; i++) {
        int r = ty + i * 8;
        out[(size_t)(c0 + r) * R + r0 + tx] = __float2half_rn(t[tx][r]);
    }
}

// ===========================================================================
// fp16 mma.sync GEMM: C[M,N] = A[M,K] @ Bt[N,K]^T, fp32 accumulate.
// CTA tile 128x128, BK=32, 256 threads (8 warps 2m x 4n), cp.async 2-stage.
// ===========================================================================
#define HKC 32
#define HSTR 40   // smem row stride in halves

__global__ __launch_bounds__(256, 2) void gemm_fp16_kernel(
    const __half* __restrict__ A, const __half* __restrict__ Bt,
    float* __restrict__ C, int M, int N, int K)
{
    __shared__ __half As[2][128 * HSTR];
    __shared__ __half Bs[2][128 * HSTR];

    const int tid  = threadIdx.x;
    const int wid  = tid >> 5;
    const int lane = tid & 31;
    const int bx = blockIdx.x, by = blockIdx.y;
    const int wm = wid & 1;
    const int wn = wid >> 1;
    const int lg = lane >> 2;
    const int lt = lane & 3;

    const __half* Ab = A  + (size_t)(by * 128) * K;
    const __half* Bb = Bt + (size_t)(bx * 128) * K;

    uint32_t sA[2], sB[2];
    sA[0] = (uint32_t)__cvta_generic_to_shared(&As[0][0]);
    sA[1] = (uint32_t)__cvta_generic_to_shared(&As[1][0]);
    sB[0] = (uint32_t)__cvta_generic_to_shared(&Bs[0][0]);
    sB[1] = (uint32_t)__cvta_generic_to_shared(&Bs[1][0]);

    float acc[4][4][4];
    #pragma unroll
    for (int i = 0; i < 4; i++)
        #pragma unroll
        for (int j = 0; j < 4; j++)
            #pragma unroll
            for (int q = 0; q < 4; q++) acc[i][j][q] = 0.f;

    const int NC = K / HKC;

    // prologue: chunk 0 -> slot 0  (128 rows x 64B per matrix)
    #pragma unroll
    for (int rep = 0; rep < 2; rep++) {
        int e = rep * 256 + tid;
        int r = e >> 2, seg = e & 3;
        cp_async16(sA[0] + (uint32_t)(r * HSTR + seg * 8) * 2, Ab + (size_t)r * K + seg * 8);
        cp_async16(sB[0] + (uint32_t)(r * HSTR + seg * 8) * 2, Bb + (size_t)r * K + seg * 8);
    }
    cp_commit();

    for (int c = 0; c < NC; c++) {
        cp_wait0();
        __syncthreads();

        if (c + 1 < NC) {
            int slot = (c + 1) & 1;
            #pragma unroll
            for (int rep = 0; rep < 2; rep++) {
                int e = rep * 256 + tid;
                int r = e >> 2, seg = e & 3;
                int koff = (c + 1) * HKC + seg * 8;
                cp_async16(sA[slot] + (uint32_t)(r * HSTR + seg * 8) * 2, Ab + (size_t)r * K + koff);
                cp_async16(sB[slot] + (uint32_t)(r * HSTR + seg * 8) * 2, Bb + (size_t)r * K + koff);
            }
            cp_commit();
        }

        const __half* Ac = As[c & 1];
        const __half* Bc = Bs[c & 1];
        #pragma unroll
        for (int ks = 0; ks < 2; ks++) {
            int kk = ks * 16 + 2 * lt;
            uint32_t a[4][4];
            #pragma unroll
            for (int mi = 0; mi < 4; mi++) {
                int r = wm * 64 + mi * 16 + lg;
                a[mi][0] = *(const uint32_t*)&Ac[r * HSTR + kk];
                a[mi][1] = *(const uint32_t*)&Ac[(r + 8) * HSTR + kk];
                a[mi][2] = *(const uint32_t*)&Ac[r * HSTR + kk + 8];
                a[mi][3] = *(const uint32_t*)&Ac[(r + 8) * HSTR + kk + 8];
            }
            #pragma unroll
            for (int ni = 0; ni < 4; ni++) {
                int nr = wn * 32 + ni * 8 + lg;
                uint32_t b0 = *(const uint32_t*)&Bc[nr * HSTR + kk];
                uint32_t b1 = *(const uint32_t*)&Bc[nr * HSTR + kk + 8];
                #pragma unroll
                for (int mi = 0; mi < 4; mi++)
                    mma_f16(acc[mi][ni][0], acc[mi][ni][1], acc[mi][ni][2], acc[mi][ni][3],
                            a[mi][0], a[mi][1], a[mi][2], a[mi][3], b0, b1);
            }
        }
    }

    #pragma unroll
    for (int mi = 0; mi < 4; mi++) {
        int row = by * 128 + wm * 64 + mi * 16 + lg;
        #pragma unroll
        for (int ni = 0; ni < 4; ni++) {
            int col = bx * 128 + wn * 32 + ni * 8 + (lt << 1);
            float2 lo = make_float2(acc[mi][ni][0], acc[mi][ni][1]);
            float2 hi = make_float2(acc[mi][ni][2], acc[mi][ni][3]);
            *(float2*)(C + (size_t)row * N + col)       = lo;
            *(float2*)(C + (size_t)(row + 8) * N + col) = hi;
        }
    }
}

// ===========================================================================
// L2-normalize q and k head-vectors in-place (fp32). One warp per vector.
// ===========================================================================
__global__ __launch_bounds__(256) void l2norm_kernel(float* __restrict__ qkv)
{
    int warp = (blockIdx.x << 3) + (threadIdx.x >> 5);
    int lane = threadIdx.x & 31;
    int row  = warp >> 5;
    int rem  = warp & 31;
    float* base = qkv + (size_t)row * QKVW + (size_t)(rem >> 4) * INNER + (size_t)(rem & 15) * DHEAD;
    float x0 = base[lane];
    float x1 = base[lane + 32];
    float ss = x0*x0 + x1*x1;
    #pragma unroll
    for (int o = 16; o; o >>= 1) ss += __shfl_xor_sync(0xffffffffu, ss, o);
    float inv = 1.0f / fmaxf(sqrtf(ss), 1e-12f);
    base[lane]      = x0 * inv;
    base[lane + 32] = x1 * inv;
}

// ===========================================================================
// Tensor-core flash attention v4 (fp16 mma, fp32 accumulate)
// CTA: 128 q rows, 256 threads (8 warps x 16 rows). Key tiles of 64.
// Smem (half): Ks[64 key][72], Vt[64 d][72], Ps[128 row][72]  = 36864 B.
// ===========================================================================
#define PH 72
#define ATT4_SMEM ((64 + 64 + 128) * PH * 2)

__global__ __launch_bounds__(256) void attn_tc_kernel(
    const float* __restrict__ qkv, __half* __restrict__ oat)
{
    extern __shared__ __half smh[];
    __half* Ks = smh;              // [key][d]   (B operand, scores)
    __half* Vt = smh + 64 * PH;    // [d][key]   (B operand, PV)
    __half* Ps = smh + 128 * PH;   // [row][key] (A operand, PV)

    const int tid  = threadIdx.x;
    const int w    = tid >> 5;
    const int lane = tid & 31;
    const int lg = lane >> 2, lt = lane & 3;
    const int qtIdx = gridDim.x - 1 - blockIdx.x;   // long CTAs first
    const int h = blockIdx.y, bb = blockIdx.z;
    const int row0 = qtIdx * 128;
    const size_t rowbase = (size_t)bb * NSEQ;
    const int R0 = row0 + w * 16;

    // --- Q fragments (prescaled, fp16 packed), resident all kernel ---
    uint32_t aq[4][4];
    {
        const float* q0 = qkv + (rowbase + R0 + lg) * QKVW + h * DHEAD;
        const float* q1 = q0 + 8 * QKVW;
        #pragma unroll
        for (int ks = 0; ks < 4; ks++) {
            int c = ks * 16 + 2 * lt;
            aq[ks][0] = pack_h2(q0[c]     * ATT_SCALE, q0[c + 1] * ATT_SCALE);
            aq[ks][1] = pack_h2(q1[c]     * ATT_SCALE, q1[c + 1] * ATT_SCALE);
            aq[ks][2] = pack_h2(q0[c + 8] * ATT_SCALE, q0[c + 9] * ATT_SCALE);
            aq[ks][3] = pack_h2(q1[c + 8] * ATT_SCALE, q1[c + 9] * ATT_SCALE);
        }
    }

    float oacc[8][4];
    #pragma unroll
    for (int ni = 0; ni < 8; ni++)
        #pragma unroll
        for (int q = 0; q < 4; q++) oacc[ni][q] = 0.f;
    float m0 = -INFINITY, m1 = -INFINITY, l0 = 0.f, l1 = 0.f;

    const int ntiles = 2 * qtIdx + 2;
    for (int jt = 0; jt < ntiles; jt++) {
        const int j0 = jt * 64;
        __syncthreads();   // previous tile's smem reads done

        // --- K/V tiles: fp32 load -> fp16 smem ---
        #pragma unroll
        for (int rep = 0; rep < 4; rep++) {
            int e  = rep * 256 + tid;     // 0..1023
            int i  = e >> 4;              // key 0..63
            int d0 = (e & 15) << 2;       // d 0..60
            const float* src = qkv + (rowbase + j0 + i) * QKVW + INNER + h * DHEAD + d0;
            float4 k4 = *(const float4*)src;
            uint2 kh;
            kh.x = pack_h2(k4.x, k4.y);
            kh.y = pack_h2(k4.z, k4.w);
            *(uint2*)&Ks[i * PH + d0] = kh;
            float4 v4 = *(const float4*)(src + INNER);
            Vt[(d0 + 0) * PH + i] = __float2half_rn(v4.x);
            Vt[(d0 + 1) * PH + i] = __float2half_rn(v4.y);
            Vt[(d0 + 2) * PH + i] = __float2half_rn(v4.z);
            Vt[(d0 + 3) * PH + i] = __float2half_rn(v4.w);
        }
        __syncthreads();

        // warps whose rows all precede this key tile are fully masked: skip
        if (j0 > R0 + 15) continue;

        // --- scores: 16 rows x 64 keys per warp ---
        float sacc[8][4];
        #pragma unroll
        for (int ni = 0; ni < 8; ni++)
            #pragma unroll
            for (int q = 0; q < 4; q++) sacc[ni][q] = 0.f;

        #pragma unroll
        for (int ks = 0; ks < 4; ks++) {
            int kk = ks * 16 + 2 * lt;
            #pragma unroll
            for (int ni = 0; ni < 8; ni++) {
                int key = ni * 8 + lg;
                uint32_t b0 = *(const uint32_t*)&Ks[key * PH + kk];
                uint32_t b1 = *(const uint32_t*)&Ks[key * PH + kk + 8];
                mma_f16(sacc[ni][0], sacc[ni][1], sacc[ni][2], sacc[ni][3],
                        aq[ks][0], aq[ks][1], aq[ks][2], aq[ks][3], b0, b1);
            }
        }

        // --- causal mask (diagonal-crossing tiles only) ---
        if (j0 + 63 > R0) {
            int ra = R0 + lg, rb = ra + 8;
            #pragma unroll
            for (int ni = 0; ni < 8; ni++) {
                int k0c = j0 + ni * 8 + 2 * lt;
                if (k0c     > ra) sacc[ni][0] = -INFINITY;
                if (k0c + 1 > ra) sacc[ni][1] = -INFINITY;
                if (k0c     > rb) sacc[ni][2] = -INFINITY;
                if (k0c + 1 > rb) sacc[ni][3] = -INFINITY;
            }
        }

        // --- online softmax (rows lg and lg+8) ---
        float mt0 = -INFINITY, mt1 = -INFINITY;
        #pragma unroll
        for (int ni = 0; ni < 8; ni++) {
            mt0 = fmaxf(mt0, fmaxf(sacc[ni][0], sacc[ni][1]));
            mt1 = fmaxf(mt1, fmaxf(sacc[ni][2], sacc[ni][3]));
        }
        mt0 = fmaxf(mt0, __shfl_xor_sync(0xffffffffu, mt0, 1));
        mt0 = fmaxf(mt0, __shfl_xor_sync(0xffffffffu, mt0, 2));
        mt1 = fmaxf(mt1, __shfl_xor_sync(0xffffffffu, mt1, 1));
        mt1 = fmaxf(mt1, __shfl_xor_sync(0xffffffffu, mt1, 2));
        float mn0 = fmaxf(m0, mt0), mn1 = fmaxf(m1, mt1);
        float c0f = __expf(m0 - mn0), c1f = __expf(m1 - mn1);
        m0 = mn0; m1 = mn1;

        float s0 = 0.f, s1 = 0.f;
        int rowa = w * 16 + lg;
        #pragma unroll
        for (int ni = 0; ni < 8; ni++) {
            __half2 h01 = __floats2half2_rn(__expf(sacc[ni][0] - m0), __expf(sacc[ni][1] - m0));
            __half2 h23 = __floats2half2_rn(__expf(sacc[ni][2] - m1), __expf(sacc[ni][3] - m1));
            float2 f01 = __half22float2(h01);
            float2 f23 = __half22float2(h23);
            s0 += f01.x + f01.y;
            s1 += f23.x + f23.y;
            int col = ni * 8 + 2 * lt;
            *(uint32_t*)&Ps[rowa * PH + col]       = *(uint32_t*)&h01;
            *(uint32_t*)&Ps[(rowa + 8) * PH + col] = *(uint32_t*)&h23;
        }
        s0 += __shfl_xor_sync(0xffffffffu, s0, 1);
        s0 += __shfl_xor_sync(0xffffffffu, s0, 2);
        s1 += __shfl_xor_sync(0xffffffffu, s1, 1);
        s1 += __shfl_xor_sync(0xffffffffu, s1, 2);
        l0 = l0 * c0f + s0;
        l1 = l1 * c1f + s1;
        #pragma unroll
        for (int ni = 0; ni < 8; ni++) {
            oacc[ni][0] *= c0f; oacc[ni][1] *= c0f;
            oacc[ni][2] *= c1f; oacc[ni][3] *= c1f;
        }
        __syncwarp();

        // --- PV: oacc += P @ V ---
        #pragma unroll
        for (int kc = 0; kc < 4; kc++) {
            int kk = kc * 16 + 2 * lt;
            uint32_t a0 = *(const uint32_t*)&Ps[rowa * PH + kk];
            uint32_t a1 = *(const uint32_t*)&Ps[(rowa + 8) * PH + kk];
            uint32_t a2 = *(const uint32_t*)&Ps[rowa * PH + kk + 8];
            uint32_t a3 = *(const uint32_t*)&Ps[(rowa + 8) * PH + kk + 8];
            #pragma unroll
            for (int ni = 0; ni < 8; ni++) {
                int dr = ni * 8 + lg;
                uint32_t b0 = *(const uint32_t*)&Vt[dr * PH + kk];
                uint32_t b1 = *(const uint32_t*)&Vt[dr * PH + kk + 8];
                mma_f16(oacc[ni][0], oacc[ni][1], oacc[ni][2], oacc[ni][3],
                        a0, a1, a2, a3, b0, b1);
            }
        }
    }

    // --- epilogue: normalize, write fp16 [b, n, h*d] ---
    float il0 = 1.0f / l0, il1 = 1.0f / l1;
    __half* outa = oat + (rowbase + R0 + lg) * INNER + h * DHEAD;
    __half* outb = outa + 8 * INNER;
    #pragma unroll
    for (int ni = 0; ni < 8; ni++) {
        int col = ni * 8 + 2 * lt;
        *(uint32_t*)&outa[col] = pack_h2(oacc[ni][0] * il0, oacc[ni][1] * il0);
        *(uint32_t*)&outb[col] = pack_h2(oacc[ni][2] * il1, oacc[ni][3] * il1);
    }
}

// ===========================================================================
extern "C" void kernel_launch(void* const* d_in, const int* in_sizes, int n_in,
                              void* d_out, int out_size)
{
    const float* x    = (const float*)d_in[0];
    const float* lnw  = (const float*)d_in[1];
    const float* lnb  = (const float*)d_in[2];
    const float* Wqkv = (const float*)d_in[3];
    const float* Wout = (const float*)d_in[4];
    float* out = (float*)d_out;

    __half *xn, *oath, *wqkvT, *woutT;
    float *qkvp;
    cudaGetSymbolAddress((void**)&xn,    g_xn_h);
    cudaGetSymbolAddress((void**)&qkvp,  g_qkv);
    cudaGetSymbolAddress((void**)&oath,  g_oat_h);
    cudaGetSymbolAddress((void**)&wqkvT, g_wqkvT);
    cudaGetSymbolAddress((void**)&woutT, g_woutT);

    cudaFuncSetAttribute(attn_tc_kernel, cudaFuncAttributeMaxDynamicSharedMemorySize, ATT4_SMEM);

    ln_kernel<<<ROWS, 256>>>(x, lnw, lnb, xn);

    transpose_kernel<<<dim3(QKVW / 32, DIM / 32), 256>>>(Wqkv, wqkvT, DIM, QKVW);
    transpose_kernel<<<dim3(INNER / 32, DIM / 32), 256>>>(Wout, woutT, DIM, INNER);

    gemm_fp16_kernel<<<dim3(QKVW / 128, ROWS / 128), 256>>>(
        xn, wqkvT, qkvp, ROWS, QKVW, DIM);

    l2norm_kernel<<<(ROWS * HEADS * 2) / 8, 256>>>(qkvp);

    attn_tc_kernel<<<dim3(NSEQ / 128, HEADS, BATCH), 256, ATT4_SMEM>>>(qkvp, oath);

    gemm_fp16_kernel<<<dim3(INNER / 128, ROWS / 128), 256>>>(
        oath, woutT, out, ROWS, INNER, DIM);
}